// round 1
// baseline (speedup 1.0000x reference)
#include <cuda_runtime.h>
#include <math.h>

// Problem constants
#define TOKENS   16384      // B*N = 16*1024
#define DMODEL   768
#define HIDDEN   3072
#define NHEADS   12
#define HEADDIM  64
#define SEQ      1024
#define BATCH    16
#define QKVDIM   2304       // 3*DMODEL

// ---------------------------------------------------------------------------
// Scratch (static __device__ — no allocation allowed)
// ---------------------------------------------------------------------------
__device__ float g_big[TOKENS * HIDDEN];   // qkv (TOKENS*2304) OR mlp hidden (TOKENS*3072)
__device__ float g_y[TOKENS * DMODEL];     // layernorm output (reused for LN1 and LN2)
__device__ float g_attn[TOKENS * DMODEL];  // attention output (pre-proj)
__device__ float g_x1[TOKENS * DMODEL];    // residual-1 output

// ---------------------------------------------------------------------------
// LayerNorm: one block per row of 768, 256 threads (3 elems/thread)
// ---------------------------------------------------------------------------
__global__ __launch_bounds__(256) void ln_kernel(
    const float* __restrict__ x, const float* __restrict__ g,
    const float* __restrict__ b, float* __restrict__ y)
{
    const int row = blockIdx.x;
    const int tid = threadIdx.x;
    const float* xr = x + (size_t)row * DMODEL;

    float v0 = xr[tid];
    float v1 = xr[tid + 256];
    float v2 = xr[tid + 512];
    float s  = v0 + v1 + v2;
    float sq = v0 * v0 + v1 * v1 + v2 * v2;

    __shared__ float red[16];
    #pragma unroll
    for (int off = 16; off; off >>= 1) {
        s  += __shfl_xor_sync(0xffffffffu, s,  off);
        sq += __shfl_xor_sync(0xffffffffu, sq, off);
    }
    const int warp = tid >> 5;
    if ((tid & 31) == 0) { red[warp] = s; red[warp + 8] = sq; }
    __syncthreads();
    float ts = 0.f, tsq = 0.f;
    #pragma unroll
    for (int i = 0; i < 8; i++) { ts += red[i]; tsq += red[i + 8]; }

    const float mean = ts * (1.0f / DMODEL);
    const float var  = tsq * (1.0f / DMODEL) - mean * mean;
    const float rstd = rsqrtf(var + 1e-6f);

    float* yr = y + (size_t)row * DMODEL;
    yr[tid]       = (v0 - mean) * rstd * g[tid]       + b[tid];
    yr[tid + 256] = (v1 - mean) * rstd * g[tid + 256] + b[tid + 256];
    yr[tid + 512] = (v2 - mean) * rstd * g[tid + 512] + b[tid + 512];
}

// ---------------------------------------------------------------------------
// NT GEMM: C[M,N] = A[M,K] @ B[N,K]^T (+bias, +residual, +gelu)
// BM=BN=128, BK=8, 256 threads, 8x8 per-thread tile.
// All problem dims divide evenly (M=16384, N in {768,2304,3072}, K in {768,3072}).
// ---------------------------------------------------------------------------
enum { EPI_NONE = 0, EPI_BIAS_RES = 1, EPI_BIAS_GELU = 2 };

template <int EPI>
__global__ __launch_bounds__(256, 2) void gemm_nt(
    const float* __restrict__ A, const float* __restrict__ B,
    const float* __restrict__ bias, const float* __restrict__ res,
    float* __restrict__ C, int M, int N, int K)
{
    __shared__ float As[8][128];
    __shared__ float Bs[8][128];

    const int tid = threadIdx.x;
    const int bm = blockIdx.y, bn = blockIdx.x;

    const int lrow = tid >> 1;          // 0..127
    const int lcol = (tid & 1) * 4;     // 0 or 4
    const float* Ag = A + (size_t)(bm * 128 + lrow) * K + lcol;
    const float* Bg = B + (size_t)(bn * 128 + lrow) * K + lcol;

    const int tm = (tid >> 4) * 8;      // row offset within tile
    const int tn = (tid & 15) * 8;      // col offset within tile

    float acc[8][8];
    #pragma unroll
    for (int i = 0; i < 8; i++)
        #pragma unroll
        for (int j = 0; j < 8; j++) acc[i][j] = 0.f;

    for (int k0 = 0; k0 < K; k0 += 8) {
        float4 av = *(const float4*)(Ag + k0);
        float4 bv = *(const float4*)(Bg + k0);
        As[lcol + 0][lrow] = av.x; As[lcol + 1][lrow] = av.y;
        As[lcol + 2][lrow] = av.z; As[lcol + 3][lrow] = av.w;
        Bs[lcol + 0][lrow] = bv.x; Bs[lcol + 1][lrow] = bv.y;
        Bs[lcol + 2][lrow] = bv.z; Bs[lcol + 3][lrow] = bv.w;
        __syncthreads();
        #pragma unroll
        for (int k = 0; k < 8; k++) {
            float4 a0 = *(const float4*)&As[k][tm];
            float4 a1 = *(const float4*)&As[k][tm + 4];
            float4 b0 = *(const float4*)&Bs[k][tn];
            float4 b1 = *(const float4*)&Bs[k][tn + 4];
            float a[8] = {a0.x, a0.y, a0.z, a0.w, a1.x, a1.y, a1.z, a1.w};
            float bb[8] = {b0.x, b0.y, b0.z, b0.w, b1.x, b1.y, b1.z, b1.w};
            #pragma unroll
            for (int i = 0; i < 8; i++)
                #pragma unroll
                for (int j = 0; j < 8; j++)
                    acc[i][j] += a[i] * bb[j];
        }
        __syncthreads();
    }

    #pragma unroll
    for (int i = 0; i < 8; i++) {
        const int gm = bm * 128 + tm + i;
        float* Crow = C + (size_t)gm * N + bn * 128 + tn;
        const float* Rrow = (EPI == EPI_BIAS_RES)
                                ? res + (size_t)gm * N + bn * 128 + tn : nullptr;
        #pragma unroll
        for (int j = 0; j < 8; j++) {
            float v = acc[i][j];
            const int gn = bn * 128 + tn + j;
            if (EPI == EPI_BIAS_RES) {
                v += bias[gn] + Rrow[j];
            } else if (EPI == EPI_BIAS_GELU) {
                v += bias[gn];
                v = 0.5f * v * (1.0f + erff(v * 0.70710678118654752f));
            }
            Crow[j] = v;
        }
    }
}

// ---------------------------------------------------------------------------
// Fused flash-style attention.
// Grid: (SEQ/64, NHEADS, BATCH). Block: 256 threads (16x16 layout).
// Each block: 64 queries x full head. Streams K/V in 64-row tiles with
// online softmax; never materializes the 1024x1024 score matrix.
// qkv layout: [token, 3*768], q at h*64, k at 768+h*64, v at 1536+h*64.
// ---------------------------------------------------------------------------
#define AST 68   // smem row stride (64 + 4 pad, keeps float4 alignment)
#define ATTN_SMEM (4 * 64 * AST * sizeof(float))

__global__ __launch_bounds__(256) void attn_kernel(
    const float* __restrict__ qkv, float* __restrict__ out)
{
    extern __shared__ float sm[];
    float* Qs = sm;
    float* Ks = sm + 64 * AST;
    float* Vs = sm + 2 * 64 * AST;
    float* Ps = sm + 3 * 64 * AST;

    const int tid = threadIdx.x;
    const int q0  = blockIdx.x * 64;
    const int h   = blockIdx.y;
    const int b   = blockIdx.z;
    const size_t tok0 = (size_t)b * SEQ;

    const int lrow = tid >> 4;          // 0..15 (loader row)
    const int lcol = (tid & 15) * 4;    // 0..60 (loader col)
    const int ty = tid >> 4;            // row group (queries ty*4..+3)
    const int tx = tid & 15;            // col group

    const float scale = 0.125f;         // 1/sqrt(64)

    // Load Q tile (pre-scaled)
    #pragma unroll
    for (int i = 0; i < 4; i++) {
        const int r = lrow + i * 16;
        float4 v = *(const float4*)(qkv + (tok0 + q0 + r) * QKVDIM + h * 64 + lcol);
        v.x *= scale; v.y *= scale; v.z *= scale; v.w *= scale;
        *(float4*)&Qs[r * AST + lcol] = v;
    }

    float m[4], l[4], o[4][4];
    #pragma unroll
    for (int i = 0; i < 4; i++) {
        m[i] = -1e30f; l[i] = 0.f;
        #pragma unroll
        for (int j = 0; j < 4; j++) o[i][j] = 0.f;
    }

    for (int kb = 0; kb < SEQ / 64; kb++) {
        __syncthreads();   // previous tile's Ks/Vs/Ps reads done (also fences Q store)
        #pragma unroll
        for (int i = 0; i < 4; i++) {
            const int r = lrow + i * 16;
            const size_t base = (tok0 + (size_t)kb * 64 + r) * QKVDIM + h * 64 + lcol;
            *(float4*)&Ks[r * AST + lcol] = *(const float4*)(qkv + base + 768);
            *(float4*)&Vs[r * AST + lcol] = *(const float4*)(qkv + base + 1536);
        }
        __syncthreads();

        // S = Qs @ Ks^T  (4x4 per thread)
        float s[4][4];
        #pragma unroll
        for (int i = 0; i < 4; i++)
            #pragma unroll
            for (int j = 0; j < 4; j++) s[i][j] = 0.f;

        #pragma unroll
        for (int d4 = 0; d4 < 64; d4 += 4) {
            float4 qv[4], kv[4];
            #pragma unroll
            for (int i = 0; i < 4; i++) qv[i] = *(const float4*)&Qs[(ty * 4 + i) * AST + d4];
            #pragma unroll
            for (int j = 0; j < 4; j++) kv[j] = *(const float4*)&Ks[(tx * 4 + j) * AST + d4];
            #pragma unroll
            for (int i = 0; i < 4; i++)
                #pragma unroll
                for (int j = 0; j < 4; j++)
                    s[i][j] += qv[i].x * kv[j].x + qv[i].y * kv[j].y
                             + qv[i].z * kv[j].z + qv[i].w * kv[j].w;
        }

        // Online softmax update (row reductions across the 16-lane tx group)
        #pragma unroll
        for (int i = 0; i < 4; i++) {
            float rm = fmaxf(fmaxf(s[i][0], s[i][1]), fmaxf(s[i][2], s[i][3]));
            #pragma unroll
            for (int off = 8; off; off >>= 1)
                rm = fmaxf(rm, __shfl_xor_sync(0xffffffffu, rm, off));
            const float mn = fmaxf(m[i], rm);
            const float alpha = __expf(m[i] - mn);
            m[i] = mn;
            float rs = 0.f;
            #pragma unroll
            for (int j = 0; j < 4; j++) { s[i][j] = __expf(s[i][j] - mn); rs += s[i][j]; }
            #pragma unroll
            for (int off = 8; off; off >>= 1)
                rs += __shfl_xor_sync(0xffffffffu, rs, off);
            l[i] = l[i] * alpha + rs;
            #pragma unroll
            for (int j = 0; j < 4; j++) o[i][j] *= alpha;
            *(float4*)&Ps[(ty * 4 + i) * AST + tx * 4] =
                make_float4(s[i][0], s[i][1], s[i][2], s[i][3]);
        }
        __syncthreads();

        // O += P @ V
        #pragma unroll
        for (int jj = 0; jj < 64; jj += 4) {
            float4 pv[4], vv[4];
            #pragma unroll
            for (int i = 0; i < 4; i++) pv[i] = *(const float4*)&Ps[(ty * 4 + i) * AST + jj];
            #pragma unroll
            for (int t = 0; t < 4; t++) vv[t] = *(const float4*)&Vs[(jj + t) * AST + tx * 4];
            #pragma unroll
            for (int i = 0; i < 4; i++) {
                o[i][0] += pv[i].x * vv[0].x + pv[i].y * vv[1].x + pv[i].z * vv[2].x + pv[i].w * vv[3].x;
                o[i][1] += pv[i].x * vv[0].y + pv[i].y * vv[1].y + pv[i].z * vv[2].y + pv[i].w * vv[3].y;
                o[i][2] += pv[i].x * vv[0].z + pv[i].y * vv[1].z + pv[i].z * vv[2].z + pv[i].w * vv[3].z;
                o[i][3] += pv[i].x * vv[0].w + pv[i].y * vv[1].w + pv[i].z * vv[2].w + pv[i].w * vv[3].w;
            }
        }
    }

    // Normalize and write out[token, h*64 + d]
    #pragma unroll
    for (int i = 0; i < 4; i++) {
        const float inv = 1.0f / l[i];
        float4 v = make_float4(o[i][0] * inv, o[i][1] * inv, o[i][2] * inv, o[i][3] * inv);
        *(float4*)(out + (tok0 + q0 + ty * 4 + i) * DMODEL + h * 64 + tx * 4) = v;
    }
}

// ---------------------------------------------------------------------------
// Launch: 7 kernels, all graph-capturable.
// ---------------------------------------------------------------------------
extern "C" void kernel_launch(void* const* d_in, const int* in_sizes, int n_in,
                              void* d_out, int out_size)
{
    (void)in_sizes; (void)n_in; (void)out_size;
    const float* x      = (const float*)d_in[0];
    const float* qkv_w  = (const float*)d_in[1];
    const float* proj_w = (const float*)d_in[2];
    const float* proj_b = (const float*)d_in[3];
    const float* fc1_w  = (const float*)d_in[4];
    const float* fc1_b  = (const float*)d_in[5];
    const float* fc2_w  = (const float*)d_in[6];
    const float* fc2_b  = (const float*)d_in[7];
    const float* n1g    = (const float*)d_in[8];
    const float* n1b    = (const float*)d_in[9];
    const float* n2g    = (const float*)d_in[10];
    const float* n2b    = (const float*)d_in[11];
    float* out = (float*)d_out;

    float *big, *y, *attn, *x1;
    cudaGetSymbolAddress((void**)&big,  g_big);
    cudaGetSymbolAddress((void**)&y,    g_y);
    cudaGetSymbolAddress((void**)&attn, g_attn);
    cudaGetSymbolAddress((void**)&x1,   g_x1);

    cudaFuncSetAttribute(attn_kernel,
                         cudaFuncAttributeMaxDynamicSharedMemorySize, (int)ATTN_SMEM);

    // x1 = x + Attn(LN1(x))
    ln_kernel<<<TOKENS, 256>>>(x, n1g, n1b, y);
    gemm_nt<EPI_NONE><<<dim3(QKVDIM / 128, TOKENS / 128), 256>>>(
        y, qkv_w, nullptr, nullptr, big, TOKENS, QKVDIM, DMODEL);
    attn_kernel<<<dim3(SEQ / 64, NHEADS, BATCH), 256, ATTN_SMEM>>>(big, attn);
    gemm_nt<EPI_BIAS_RES><<<dim3(DMODEL / 128, TOKENS / 128), 256>>>(
        attn, proj_w, proj_b, x, x1, TOKENS, DMODEL, DMODEL);

    // out = x1 + MLP(LN2(x1))
    ln_kernel<<<TOKENS, 256>>>(x1, n2g, n2b, y);
    gemm_nt<EPI_BIAS_GELU><<<dim3(HIDDEN / 128, TOKENS / 128), 256>>>(
        y, fc1_w, fc1_b, nullptr, big, TOKENS, HIDDEN, DMODEL);
    gemm_nt<EPI_BIAS_RES><<<dim3(DMODEL / 128, TOKENS / 128), 256>>>(
        big, fc2_w, fc2_b, x1, out, TOKENS, DMODEL, HIDDEN);
}

// round 2
// speedup vs baseline: 2.0121x; 2.0121x over previous
#include <cuda_runtime.h>
#include <math.h>
#include <stdint.h>

// Problem constants
#define TOKENS   16384      // B*N = 16*1024
#define DMODEL   768
#define HIDDEN   3072
#define NHEADS   12
#define HEADDIM  64
#define SEQ      1024
#define BATCH    16
#define QKVDIM   2304       // 3*DMODEL

// ---------------------------------------------------------------------------
// Scratch (static __device__ — no allocation allowed)
// ---------------------------------------------------------------------------
__device__ float g_big[TOKENS * HIDDEN];   // qkv (TOKENS*2304) OR mlp hidden (TOKENS*3072)
__device__ float g_y[TOKENS * DMODEL];     // layernorm output
__device__ float g_attn[TOKENS * DMODEL];  // attention output (pre-proj)
__device__ float g_x1[TOKENS * DMODEL];    // residual-1 output

// ---------------------------------------------------------------------------
// LayerNorm: one block per row of 768, 256 threads (3 elems/thread)
// ---------------------------------------------------------------------------
__global__ __launch_bounds__(256) void ln_kernel(
    const float* __restrict__ x, const float* __restrict__ g,
    const float* __restrict__ b, float* __restrict__ y)
{
    const int row = blockIdx.x;
    const int tid = threadIdx.x;
    const float* xr = x + (size_t)row * DMODEL;

    float v0 = xr[tid];
    float v1 = xr[tid + 256];
    float v2 = xr[tid + 512];
    float s  = v0 + v1 + v2;
    float sq = v0 * v0 + v1 * v1 + v2 * v2;

    __shared__ float red[16];
    #pragma unroll
    for (int off = 16; off; off >>= 1) {
        s  += __shfl_xor_sync(0xffffffffu, s,  off);
        sq += __shfl_xor_sync(0xffffffffu, sq, off);
    }
    const int warp = tid >> 5;
    if ((tid & 31) == 0) { red[warp] = s; red[warp + 8] = sq; }
    __syncthreads();
    float ts = 0.f, tsq = 0.f;
    #pragma unroll
    for (int i = 0; i < 8; i++) { ts += red[i]; tsq += red[i + 8]; }

    const float mean = ts * (1.0f / DMODEL);
    const float var  = tsq * (1.0f / DMODEL) - mean * mean;
    const float rstd = rsqrtf(var + 1e-6f);

    float* yr = y + (size_t)row * DMODEL;
    yr[tid]       = (v0 - mean) * rstd * g[tid]       + b[tid];
    yr[tid + 256] = (v1 - mean) * rstd * g[tid + 256] + b[tid + 256];
    yr[tid + 512] = (v2 - mean) * rstd * g[tid + 512] + b[tid + 512];
}

// ---------------------------------------------------------------------------
// TF32 tensor-core NT GEMM: C[M,N] = A[M,K] @ B[N,K]^T (+bias/res/gelu)
// 128x128x16 CTA tile, 256 threads = 8 warps (2x4), warp tile 64x32 as
// 4x4 grid of m16n8k8 tf32 mma.sync.
// Smem m-major with stride BK+4=20 -> fragment LDS is 32-bank conflict-free.
// ---------------------------------------------------------------------------
#define BK 16
#define KST 20   // BK + 4 pad

enum { EPI_NONE = 0, EPI_BIAS_RES = 1, EPI_BIAS_GELU = 2 };

__device__ __forceinline__ uint32_t f2tf32(float x) {
    uint32_t u;
    asm("cvt.rna.tf32.f32 %0, %1;" : "=r"(u) : "f"(x));
    return u;
}

__device__ __forceinline__ void mma_tf32(float* c, const uint32_t* a, const uint32_t* b) {
    asm volatile(
        "mma.sync.aligned.m16n8k8.row.col.f32.tf32.tf32.f32 "
        "{%0,%1,%2,%3}, {%4,%5,%6,%7}, {%8,%9}, {%0,%1,%2,%3};"
        : "+f"(c[0]), "+f"(c[1]), "+f"(c[2]), "+f"(c[3])
        : "r"(a[0]), "r"(a[1]), "r"(a[2]), "r"(a[3]), "r"(b[0]), "r"(b[1]));
}

template <int EPI>
__global__ __launch_bounds__(256, 2) void gemm_tf32(
    const float* __restrict__ A, const float* __restrict__ B,
    const float* __restrict__ bias, const float* __restrict__ res,
    float* __restrict__ C, int M, int N, int K)
{
    __shared__ uint32_t As[128][KST];
    __shared__ uint32_t Bs[128][KST];

    const int tid = threadIdx.x;
    const int bm = blockIdx.y, bn = blockIdx.x;

    // gmem loader mapping: each thread loads 2 float4 from A and 2 from B
    const int lr = tid >> 2;            // 0..63
    const int lc = (tid & 3) * 4;       // 0,4,8,12
    const float* Ag0 = A + (size_t)(bm * 128 + lr) * K + lc;
    const float* Ag1 = Ag0 + (size_t)64 * K;
    const float* Bg0 = B + (size_t)(bn * 128 + lr) * K + lc;
    const float* Bg1 = Bg0 + (size_t)64 * K;

    // compute mapping
    const int wid = tid >> 5, lane = tid & 31;
    const int wm = (wid >> 2) * 64;     // warp row offset (0/64)
    const int wn = (wid & 3) * 32;      // warp col offset (0/32/64/96)
    const int qr = lane >> 2;           // 0..7
    const int qc = lane & 3;            // 0..3

    float acc[4][4][4];
    #pragma unroll
    for (int i = 0; i < 4; i++)
        #pragma unroll
        for (int j = 0; j < 4; j++)
            #pragma unroll
            for (int t = 0; t < 4; t++) acc[i][j][t] = 0.f;

    const int kTiles = K / BK;

    float4 fa0 = *(const float4*)Ag0;
    float4 fa1 = *(const float4*)Ag1;
    float4 fb0 = *(const float4*)Bg0;
    float4 fb1 = *(const float4*)Bg1;

    #define STS_TILE()                                                                  \
        do {                                                                            \
            *(uint4*)&As[lr][lc]      = make_uint4(f2tf32(fa0.x), f2tf32(fa0.y),        \
                                                   f2tf32(fa0.z), f2tf32(fa0.w));       \
            *(uint4*)&As[lr + 64][lc] = make_uint4(f2tf32(fa1.x), f2tf32(fa1.y),        \
                                                   f2tf32(fa1.z), f2tf32(fa1.w));       \
            *(uint4*)&Bs[lr][lc]      = make_uint4(f2tf32(fb0.x), f2tf32(fb0.y),        \
                                                   f2tf32(fb0.z), f2tf32(fb0.w));       \
            *(uint4*)&Bs[lr + 64][lc] = make_uint4(f2tf32(fb1.x), f2tf32(fb1.y),        \
                                                   f2tf32(fb1.z), f2tf32(fb1.w));       \
        } while (0)

    STS_TILE();
    __syncthreads();

    for (int kt = 0; kt < kTiles; kt++) {
        if (kt + 1 < kTiles) {
            const int off = (kt + 1) * BK;
            fa0 = *(const float4*)(Ag0 + off);
            fa1 = *(const float4*)(Ag1 + off);
            fb0 = *(const float4*)(Bg0 + off);
            fb1 = *(const float4*)(Bg1 + off);
        }
        #pragma unroll
        for (int s = 0; s < 2; s++) {
            const int k0 = s * 8 + qc;
            uint32_t af[4][4], bf[4][2];
            #pragma unroll
            for (int i = 0; i < 4; i++) {
                const int m0 = wm + i * 16 + qr;
                af[i][0] = As[m0][k0];
                af[i][1] = As[m0 + 8][k0];
                af[i][2] = As[m0][k0 + 4];
                af[i][3] = As[m0 + 8][k0 + 4];
            }
            #pragma unroll
            for (int j = 0; j < 4; j++) {
                const int n0 = wn + j * 8 + qr;
                bf[j][0] = Bs[n0][k0];
                bf[j][1] = Bs[n0][k0 + 4];
            }
            #pragma unroll
            for (int i = 0; i < 4; i++)
                #pragma unroll
                for (int j = 0; j < 4; j++)
                    mma_tf32(acc[i][j], af[i], bf[j]);
        }
        if (kt + 1 < kTiles) {
            __syncthreads();
            STS_TILE();
            __syncthreads();
        }
    }

    // Epilogue: each (i,j) tile -> 2 float2 stores (rows qr, qr+8; cols 2*qc,+1)
    #pragma unroll
    for (int i = 0; i < 4; i++) {
        const int gr0 = bm * 128 + wm + i * 16 + qr;
        #pragma unroll
        for (int j = 0; j < 4; j++) {
            const int gc = bn * 128 + wn + j * 8 + qc * 2;
            float v0 = acc[i][j][0], v1 = acc[i][j][1];
            float v2 = acc[i][j][2], v3 = acc[i][j][3];
            if (EPI == EPI_BIAS_RES) {
                const float b0 = bias[gc], b1 = bias[gc + 1];
                const float* r0 = res + (size_t)gr0 * N + gc;
                const float* r1 = res + (size_t)(gr0 + 8) * N + gc;
                v0 += b0 + r0[0]; v1 += b1 + r0[1];
                v2 += b0 + r1[0]; v3 += b1 + r1[1];
            } else if (EPI == EPI_BIAS_GELU) {
                const float b0 = bias[gc], b1 = bias[gc + 1];
                v0 += b0; v1 += b1; v2 += b0; v3 += b1;
                v0 = 0.5f * v0 * (1.0f + erff(v0 * 0.70710678118654752f));
                v1 = 0.5f * v1 * (1.0f + erff(v1 * 0.70710678118654752f));
                v2 = 0.5f * v2 * (1.0f + erff(v2 * 0.70710678118654752f));
                v3 = 0.5f * v3 * (1.0f + erff(v3 * 0.70710678118654752f));
            }
            *(float2*)(C + (size_t)gr0 * N + gc)       = make_float2(v0, v1);
            *(float2*)(C + (size_t)(gr0 + 8) * N + gc) = make_float2(v2, v3);
        }
    }
}

// ---------------------------------------------------------------------------
// Fused flash-style attention (unchanged from R1).
// ---------------------------------------------------------------------------
#define AST 68
#define ATTN_SMEM (4 * 64 * AST * sizeof(float))

__global__ __launch_bounds__(256) void attn_kernel(
    const float* __restrict__ qkv, float* __restrict__ out)
{
    extern __shared__ float sm[];
    float* Qs = sm;
    float* Ks = sm + 64 * AST;
    float* Vs = sm + 2 * 64 * AST;
    float* Ps = sm + 3 * 64 * AST;

    const int tid = threadIdx.x;
    const int q0  = blockIdx.x * 64;
    const int h   = blockIdx.y;
    const int b   = blockIdx.z;
    const size_t tok0 = (size_t)b * SEQ;

    const int lrow = tid >> 4;
    const int lcol = (tid & 15) * 4;
    const int ty = tid >> 4;
    const int tx = tid & 15;

    const float scale = 0.125f;

    #pragma unroll
    for (int i = 0; i < 4; i++) {
        const int r = lrow + i * 16;
        float4 v = *(const float4*)(qkv + (tok0 + q0 + r) * QKVDIM + h * 64 + lcol);
        v.x *= scale; v.y *= scale; v.z *= scale; v.w *= scale;
        *(float4*)&Qs[r * AST + lcol] = v;
    }

    float m[4], l[4], o[4][4];
    #pragma unroll
    for (int i = 0; i < 4; i++) {
        m[i] = -1e30f; l[i] = 0.f;
        #pragma unroll
        for (int j = 0; j < 4; j++) o[i][j] = 0.f;
    }

    for (int kb = 0; kb < SEQ / 64; kb++) {
        __syncthreads();
        #pragma unroll
        for (int i = 0; i < 4; i++) {
            const int r = lrow + i * 16;
            const size_t base = (tok0 + (size_t)kb * 64 + r) * QKVDIM + h * 64 + lcol;
            *(float4*)&Ks[r * AST + lcol] = *(const float4*)(qkv + base + 768);
            *(float4*)&Vs[r * AST + lcol] = *(const float4*)(qkv + base + 1536);
        }
        __syncthreads();

        float s[4][4];
        #pragma unroll
        for (int i = 0; i < 4; i++)
            #pragma unroll
            for (int j = 0; j < 4; j++) s[i][j] = 0.f;

        #pragma unroll
        for (int d4 = 0; d4 < 64; d4 += 4) {
            float4 qv[4], kv[4];
            #pragma unroll
            for (int i = 0; i < 4; i++) qv[i] = *(const float4*)&Qs[(ty * 4 + i) * AST + d4];
            #pragma unroll
            for (int j = 0; j < 4; j++) kv[j] = *(const float4*)&Ks[(tx * 4 + j) * AST + d4];
            #pragma unroll
            for (int i = 0; i < 4; i++)
                #pragma unroll
                for (int j = 0; j < 4; j++)
                    s[i][j] += qv[i].x * kv[j].x + qv[i].y * kv[j].y
                             + qv[i].z * kv[j].z + qv[i].w * kv[j].w;
        }

        #pragma unroll
        for (int i = 0; i < 4; i++) {
            float rm = fmaxf(fmaxf(s[i][0], s[i][1]), fmaxf(s[i][2], s[i][3]));
            #pragma unroll
            for (int off = 8; off; off >>= 1)
                rm = fmaxf(rm, __shfl_xor_sync(0xffffffffu, rm, off));
            const float mn = fmaxf(m[i], rm);
            const float alpha = __expf(m[i] - mn);
            m[i] = mn;
            float rs = 0.f;
            #pragma unroll
            for (int j = 0; j < 4; j++) { s[i][j] = __expf(s[i][j] - mn); rs += s[i][j]; }
            #pragma unroll
            for (int off = 8; off; off >>= 1)
                rs += __shfl_xor_sync(0xffffffffu, rs, off);
            l[i] = l[i] * alpha + rs;
            #pragma unroll
            for (int j = 0; j < 4; j++) o[i][j] *= alpha;
            *(float4*)&Ps[(ty * 4 + i) * AST + tx * 4] =
                make_float4(s[i][0], s[i][1], s[i][2], s[i][3]);
        }
        __syncthreads();

        #pragma unroll
        for (int jj = 0; jj < 64; jj += 4) {
            float4 pv[4], vv[4];
            #pragma unroll
            for (int i = 0; i < 4; i++) pv[i] = *(const float4*)&Ps[(ty * 4 + i) * AST + jj];
            #pragma unroll
            for (int t = 0; t < 4; t++) vv[t] = *(const float4*)&Vs[(jj + t) * AST + tx * 4];
            #pragma unroll
            for (int i = 0; i < 4; i++) {
                o[i][0] += pv[i].x * vv[0].x + pv[i].y * vv[1].x + pv[i].z * vv[2].x + pv[i].w * vv[3].x;
                o[i][1] += pv[i].x * vv[0].y + pv[i].y * vv[1].y + pv[i].z * vv[2].y + pv[i].w * vv[3].y;
                o[i][2] += pv[i].x * vv[0].z + pv[i].y * vv[1].z + pv[i].z * vv[2].z + pv[i].w * vv[3].z;
                o[i][3] += pv[i].x * vv[0].w + pv[i].y * vv[1].w + pv[i].z * vv[2].w + pv[i].w * vv[3].w;
            }
        }
    }

    #pragma unroll
    for (int i = 0; i < 4; i++) {
        const float inv = 1.0f / l[i];
        float4 v = make_float4(o[i][0] * inv, o[i][1] * inv, o[i][2] * inv, o[i][3] * inv);
        *(float4*)(out + (tok0 + q0 + ty * 4 + i) * DMODEL + h * 64 + tx * 4) = v;
    }
}

// ---------------------------------------------------------------------------
// Launch: 7 kernels, all graph-capturable.
// ---------------------------------------------------------------------------
extern "C" void kernel_launch(void* const* d_in, const int* in_sizes, int n_in,
                              void* d_out, int out_size)
{
    (void)in_sizes; (void)n_in; (void)out_size;
    const float* x      = (const float*)d_in[0];
    const float* qkv_w  = (const float*)d_in[1];
    const float* proj_w = (const float*)d_in[2];
    const float* proj_b = (const float*)d_in[3];
    const float* fc1_w  = (const float*)d_in[4];
    const float* fc1_b  = (const float*)d_in[5];
    const float* fc2_w  = (const float*)d_in[6];
    const float* fc2_b  = (const float*)d_in[7];
    const float* n1g    = (const float*)d_in[8];
    const float* n1b    = (const float*)d_in[9];
    const float* n2g    = (const float*)d_in[10];
    const float* n2b    = (const float*)d_in[11];
    float* out = (float*)d_out;

    float *big, *y, *attn, *x1;
    cudaGetSymbolAddress((void**)&big,  g_big);
    cudaGetSymbolAddress((void**)&y,    g_y);
    cudaGetSymbolAddress((void**)&attn, g_attn);
    cudaGetSymbolAddress((void**)&x1,   g_x1);

    cudaFuncSetAttribute(attn_kernel,
                         cudaFuncAttributeMaxDynamicSharedMemorySize, (int)ATTN_SMEM);

    // x1 = x + Attn(LN1(x))
    ln_kernel<<<TOKENS, 256>>>(x, n1g, n1b, y);
    gemm_tf32<EPI_NONE><<<dim3(QKVDIM / 128, TOKENS / 128), 256>>>(
        y, qkv_w, nullptr, nullptr, big, TOKENS, QKVDIM, DMODEL);
    attn_kernel<<<dim3(SEQ / 64, NHEADS, BATCH), 256, ATTN_SMEM>>>(big, attn);
    gemm_tf32<EPI_BIAS_RES><<<dim3(DMODEL / 128, TOKENS / 128), 256>>>(
        attn, proj_w, proj_b, x, x1, TOKENS, DMODEL, DMODEL);

    // out = x1 + MLP(LN2(x1))
    ln_kernel<<<TOKENS, 256>>>(x1, n2g, n2b, y);
    gemm_tf32<EPI_BIAS_GELU><<<dim3(HIDDEN / 128, TOKENS / 128), 256>>>(
        y, fc1_w, fc1_b, nullptr, big, TOKENS, HIDDEN, DMODEL);
    gemm_tf32<EPI_BIAS_RES><<<dim3(DMODEL / 128, TOKENS / 128), 256>>>(
        big, fc2_w, fc2_b, x1, out, TOKENS, DMODEL, HIDDEN);
}

// round 5
// speedup vs baseline: 3.5447x; 1.7617x over previous
#include <cuda_runtime.h>
#include <math.h>
#include <stdint.h>

// Problem constants
#define TOKENS   16384      // B*N
#define DMODEL   768
#define HIDDEN   3072
#define NHEADS   12
#define SEQ      1024
#define BATCH    16
#define QKVDIM   2304

// ---------------------------------------------------------------------------
// Scratch (static __device__ — no allocation allowed)
// ---------------------------------------------------------------------------
__device__ float g_big[TOKENS * HIDDEN];   // qkv OR mlp hidden
__device__ float g_y[TOKENS * DMODEL];     // layernorm output (tf32-rounded)
__device__ float g_attn[TOKENS * DMODEL];  // attention output (tf32-rounded)
__device__ float g_x1[TOKENS * DMODEL];    // residual-1 (exact fp32)
// tf32-rounded weights: qkv | proj | fc1 | fc2
#define W_QKV  0
#define W_PROJ (W_QKV + QKVDIM * DMODEL)
#define W_FC1  (W_PROJ + DMODEL * DMODEL)
#define W_FC2  (W_FC1 + HIDDEN * DMODEL)
#define W_TOT  (W_FC2 + DMODEL * HIDDEN)
__device__ float g_w[W_TOT];

// ---------------------------------------------------------------------------
// tf32 helpers
// ---------------------------------------------------------------------------
__device__ __forceinline__ uint32_t f2tf32(float x) {
    uint32_t u;
    asm("cvt.rna.tf32.f32 %0, %1;" : "=r"(u) : "f"(x));
    return u;
}
__device__ __forceinline__ float f2tf32f(float x) { return __uint_as_float(f2tf32(x)); }

__device__ __forceinline__ void mma_tf32(float* c, const uint32_t* a, const uint32_t* b) {
    asm volatile(
        "mma.sync.aligned.m16n8k8.row.col.f32.tf32.tf32.f32 "
        "{%0,%1,%2,%3}, {%4,%5,%6,%7}, {%8,%9}, {%0,%1,%2,%3};"
        : "+f"(c[0]), "+f"(c[1]), "+f"(c[2]), "+f"(c[3])
        : "r"(a[0]), "r"(a[1]), "r"(a[2]), "r"(a[3]), "r"(b[0]), "r"(b[1]));
}

__device__ __forceinline__ void cpa16(uint32_t dst, const float* src) {
    asm volatile("cp.async.cg.shared.global [%0], [%1], 16;\n" :: "r"(dst), "l"(src));
}

// ---------------------------------------------------------------------------
// Weight rounding: dst = tf32_rna(src), float4 elementwise
// ---------------------------------------------------------------------------
__global__ __launch_bounds__(256) void round_w_kernel(
    const float* __restrict__ src, float* __restrict__ dst, int n4)
{
    int i = blockIdx.x * blockDim.x + threadIdx.x;
    if (i < n4) {
        float4 v = ((const float4*)src)[i];
        v.x = f2tf32f(v.x); v.y = f2tf32f(v.y);
        v.z = f2tf32f(v.z); v.w = f2tf32f(v.w);
        ((float4*)dst)[i] = v;
    }
}

// ---------------------------------------------------------------------------
// LayerNorm (writes tf32-rounded output — it only feeds GEMM A operands)
// ---------------------------------------------------------------------------
__global__ __launch_bounds__(256) void ln_kernel(
    const float* __restrict__ x, const float* __restrict__ g,
    const float* __restrict__ b, float* __restrict__ y)
{
    const int row = blockIdx.x;
    const int tid = threadIdx.x;
    const float* xr = x + (size_t)row * DMODEL;

    float v0 = xr[tid];
    float v1 = xr[tid + 256];
    float v2 = xr[tid + 512];
    float s  = v0 + v1 + v2;
    float sq = v0 * v0 + v1 * v1 + v2 * v2;

    __shared__ float red[16];
    #pragma unroll
    for (int off = 16; off; off >>= 1) {
        s  += __shfl_xor_sync(0xffffffffu, s,  off);
        sq += __shfl_xor_sync(0xffffffffu, sq, off);
    }
    const int warp = tid >> 5;
    if ((tid & 31) == 0) { red[warp] = s; red[warp + 8] = sq; }
    __syncthreads();
    float ts = 0.f, tsq = 0.f;
    #pragma unroll
    for (int i = 0; i < 8; i++) { ts += red[i]; tsq += red[i + 8]; }

    const float mean = ts * (1.0f / DMODEL);
    const float var  = tsq * (1.0f / DMODEL) - mean * mean;
    const float rstd = rsqrtf(var + 1e-6f);

    float* yr = y + (size_t)row * DMODEL;
    yr[tid]       = f2tf32f((v0 - mean) * rstd * g[tid]       + b[tid]);
    yr[tid + 256] = f2tf32f((v1 - mean) * rstd * g[tid + 256] + b[tid + 256]);
    yr[tid + 512] = f2tf32f((v2 - mean) * rstd * g[tid + 512] + b[tid + 512]);
}

// ---------------------------------------------------------------------------
// TF32 NT GEMM with cp.async 3-stage pipeline. Inputs pre-rounded to tf32.
// 128x128x16 CTA, 256 thr = 8 warps (2x4), warp 64x32, 4x4 m16n8k8.
// ---------------------------------------------------------------------------
#define BK 16
#define KST 20
#define STAGES 3
#define STAGE_WORDS (2 * 128 * KST)
#define GEMM_SMEM (STAGES * STAGE_WORDS * 4)

enum { EPI_NONE = 0, EPI_BIAS_RES = 1, EPI_BIAS_GELU = 2 };

template <int EPI>
__global__ __launch_bounds__(256, 2) void gemm_tf32(
    const float* __restrict__ A, const float* __restrict__ B,
    const float* __restrict__ bias, const float* __restrict__ res,
    float* __restrict__ C, int M, int N, int K)
{
    extern __shared__ float sm[];

    const int tid = threadIdx.x;
    const int bm = blockIdx.y, bn = blockIdx.x;

    const int lr = tid >> 2;
    const int lc = (tid & 3) * 4;
    const float* Ag0 = A + (size_t)(bm * 128 + lr) * K + lc;
    const float* Ag1 = Ag0 + (size_t)64 * K;
    const float* Bg0 = B + (size_t)(bn * 128 + lr) * K + lc;
    const float* Bg1 = Bg0 + (size_t)64 * K;

    const uint32_t sbase = (uint32_t)__cvta_generic_to_shared(sm);
    const uint32_t dA = (lr * KST + lc) * 4;
    const uint32_t dB = (128 * KST + lr * KST + lc) * 4;
    const uint32_t rowHop = 64 * KST * 4;

    const int wid = tid >> 5, lane = tid & 31;
    const int wm = (wid >> 2) * 64;
    const int wn = (wid & 3) * 32;
    const int qr = lane >> 2;
    const int qc = lane & 3;

    float acc[4][4][4];
    #pragma unroll
    for (int i = 0; i < 4; i++)
        #pragma unroll
        for (int j = 0; j < 4; j++)
            #pragma unroll
            for (int t = 0; t < 4; t++) acc[i][j][t] = 0.f;

    const int kTiles = K / BK;

    #pragma unroll
    for (int p = 0; p < STAGES - 1; p++) {
        const uint32_t sb = sbase + p * STAGE_WORDS * 4;
        cpa16(sb + dA,          Ag0 + p * BK);
        cpa16(sb + dA + rowHop, Ag1 + p * BK);
        cpa16(sb + dB,          Bg0 + p * BK);
        cpa16(sb + dB + rowHop, Bg1 + p * BK);
        asm volatile("cp.async.commit_group;\n");
    }

    for (int kt = 0; kt < kTiles; kt++) {
        asm volatile("cp.async.wait_group %0;\n" :: "n"(STAGES - 2));
        __syncthreads();

        const int nk = kt + STAGES - 1;
        if (nk < kTiles) {
            const uint32_t sb = sbase + (nk % STAGES) * STAGE_WORDS * 4;
            cpa16(sb + dA,          Ag0 + nk * BK);
            cpa16(sb + dA + rowHop, Ag1 + nk * BK);
            cpa16(sb + dB,          Bg0 + nk * BK);
            cpa16(sb + dB + rowHop, Bg1 + nk * BK);
        }
        asm volatile("cp.async.commit_group;\n");

        const float* As = sm + (kt % STAGES) * STAGE_WORDS;
        const float* Bs = As + 128 * KST;

        #pragma unroll
        for (int s = 0; s < 2; s++) {
            const int k0 = s * 8 + qc;
            uint32_t af[4][4], bf[4][2];
            #pragma unroll
            for (int i = 0; i < 4; i++) {
                const int m0 = wm + i * 16 + qr;
                af[i][0] = __float_as_uint(As[m0 * KST + k0]);
                af[i][1] = __float_as_uint(As[(m0 + 8) * KST + k0]);
                af[i][2] = __float_as_uint(As[m0 * KST + k0 + 4]);
                af[i][3] = __float_as_uint(As[(m0 + 8) * KST + k0 + 4]);
            }
            #pragma unroll
            for (int j = 0; j < 4; j++) {
                const int n0 = wn + j * 8 + qr;
                bf[j][0] = __float_as_uint(Bs[n0 * KST + k0]);
                bf[j][1] = __float_as_uint(Bs[n0 * KST + k0 + 4]);
            }
            #pragma unroll
            for (int i = 0; i < 4; i++)
                #pragma unroll
                for (int j = 0; j < 4; j++)
                    mma_tf32(acc[i][j], af[i], bf[j]);
        }
    }

    #pragma unroll
    for (int i = 0; i < 4; i++) {
        const int gr0 = bm * 128 + wm + i * 16 + qr;
        #pragma unroll
        for (int j = 0; j < 4; j++) {
            const int gc = bn * 128 + wn + j * 8 + qc * 2;
            float v0 = acc[i][j][0], v1 = acc[i][j][1];
            float v2 = acc[i][j][2], v3 = acc[i][j][3];
            if (EPI == EPI_BIAS_RES) {
                const float b0 = bias[gc], b1 = bias[gc + 1];
                const float* r0 = res + (size_t)gr0 * N + gc;
                const float* r1 = res + (size_t)(gr0 + 8) * N + gc;
                v0 += b0 + r0[0]; v1 += b1 + r0[1];
                v2 += b0 + r1[0]; v3 += b1 + r1[1];
            } else if (EPI == EPI_BIAS_GELU) {
                const float b0 = bias[gc], b1 = bias[gc + 1];
                v0 += b0; v1 += b1; v2 += b0; v3 += b1;
                v0 = f2tf32f(0.5f * v0 * (1.0f + erff(v0 * 0.70710678118654752f)));
                v1 = f2tf32f(0.5f * v1 * (1.0f + erff(v1 * 0.70710678118654752f)));
                v2 = f2tf32f(0.5f * v2 * (1.0f + erff(v2 * 0.70710678118654752f)));
                v3 = f2tf32f(0.5f * v3 * (1.0f + erff(v3 * 0.70710678118654752f)));
            }
            *(float2*)(C + (size_t)gr0 * N + gc)       = make_float2(v0, v1);
            *(float2*)(C + (size_t)(gr0 + 8) * N + gc) = make_float2(v2, v3);
        }
    }
}

// ---------------------------------------------------------------------------
// Tensor-core flash attention. 64 queries/CTA, 4 warps (128 thr).
// Warp w owns query rows w*16 + {qr, qr+8}. Q frags register-resident.
// Ks: K tile [64 key][64 d]; Vs: V^T [64 d][64 key]; Ps: P [64 q][64 key].
// FIXED R4 bug: staging loops now cover the FULL 64x64 tile
// (c < 1024, r = c>>4, col = (c&15)*4). R3/R4 covered only 64x16.
// ---------------------------------------------------------------------------
#define AS2 68
#define ATTN_SMEM (3 * 64 * AS2 * 4)

__global__ __launch_bounds__(128, 3) void attn_tc(
    const float* __restrict__ qkv, float* __restrict__ out)
{
    extern __shared__ float smm[];
    float* Ks = smm;
    float* Vs = smm + 64 * AS2;
    float* Ps = smm + 2 * 64 * AS2;

    const int tid = threadIdx.x;
    const int wid = tid >> 5, lane = tid & 31;
    const int qr = lane >> 2, qc = lane & 3;
    const int q0 = blockIdx.x * 64;
    const int h  = blockIdx.y;
    const int b  = blockIdx.z;
    const size_t tok0 = (size_t)b * SEQ;

    const float* qbase = qkv + (tok0 + q0) * QKVDIM + h * 64;
    const float* kbase = qkv + tok0 * QKVDIM + 768 + h * 64;
    const float* vbase = qkv + tok0 * QKVDIM + 1536 + h * 64;

    // Stage Q (scaled, tf32) into Ks: 64 rows x 16 float4s = 1024 float4s
    #pragma unroll
    for (int c = tid; c < 1024; c += 128) {
        const int r = c >> 4, col = (c & 15) * 4;
        float4 v = *(const float4*)(qbase + (size_t)r * QKVDIM + col);
        *(uint4*)&Ks[r * AS2 + col] =
            make_uint4(f2tf32(v.x * 0.125f), f2tf32(v.y * 0.125f),
                       f2tf32(v.z * 0.125f), f2tf32(v.w * 0.125f));
    }
    __syncthreads();

    const int mrow = wid * 16 + qr;
    uint32_t qa[8][4];
    #pragma unroll
    for (int s = 0; s < 8; s++) {
        const int k0 = s * 8 + qc;
        qa[s][0] = __float_as_uint(Ks[mrow * AS2 + k0]);
        qa[s][1] = __float_as_uint(Ks[(mrow + 8) * AS2 + k0]);
        qa[s][2] = __float_as_uint(Ks[mrow * AS2 + k0 + 4]);
        qa[s][3] = __float_as_uint(Ks[(mrow + 8) * AS2 + k0 + 4]);
    }

    float o[8][4];
    #pragma unroll
    for (int d = 0; d < 8; d++)
        #pragma unroll
        for (int t = 0; t < 4; t++) o[d][t] = 0.f;
    float m0r = -1e30f, m1r = -1e30f, l0 = 0.f, l1 = 0.f;

    for (int kb = 0; kb < SEQ / 64; kb++) {
        __syncthreads();   // everyone done with previous Ks/Vs (and Q frags)
        // K tile: Ks[key][d]
        #pragma unroll
        for (int c = tid; c < 1024; c += 128) {
            const int r = c >> 4, col = (c & 15) * 4;
            float4 v = *(const float4*)(kbase + (size_t)(kb * 64 + r) * QKVDIM + col);
            *(uint4*)&Ks[r * AS2 + col] =
                make_uint4(f2tf32(v.x), f2tf32(v.y), f2tf32(v.z), f2tf32(v.w));
        }
        // V tile transposed: Vs[d][key]
        #pragma unroll
        for (int c = tid; c < 1024; c += 128) {
            const int j = c >> 4, col = (c & 15) * 4;
            float4 v = *(const float4*)(vbase + (size_t)(kb * 64 + j) * QKVDIM + col);
            Vs[(col + 0) * AS2 + j] = __uint_as_float(f2tf32(v.x));
            Vs[(col + 1) * AS2 + j] = __uint_as_float(f2tf32(v.y));
            Vs[(col + 2) * AS2 + j] = __uint_as_float(f2tf32(v.z));
            Vs[(col + 3) * AS2 + j] = __uint_as_float(f2tf32(v.w));
        }
        __syncthreads();

        // S = Q @ K^T : 8 key tiles of n8
        float s[8][4];
        #pragma unroll
        for (int j = 0; j < 8; j++)
            #pragma unroll
            for (int t = 0; t < 4; t++) s[j][t] = 0.f;
        #pragma unroll
        for (int ks = 0; ks < 8; ks++) {
            const int k0 = ks * 8 + qc;
            #pragma unroll
            for (int j = 0; j < 8; j++) {
                uint32_t bf[2];
                const int n0 = j * 8 + qr;
                bf[0] = __float_as_uint(Ks[n0 * AS2 + k0]);
                bf[1] = __float_as_uint(Ks[n0 * AS2 + k0 + 4]);
                mma_tf32(s[j], qa[ks], bf);
            }
        }

        // Online softmax (rows qr and qr+8; reduce across qc lanes)
        float rm0 = -1e30f, rm1 = -1e30f;
        #pragma unroll
        for (int j = 0; j < 8; j++) {
            rm0 = fmaxf(rm0, fmaxf(s[j][0], s[j][1]));
            rm1 = fmaxf(rm1, fmaxf(s[j][2], s[j][3]));
        }
        rm0 = fmaxf(rm0, __shfl_xor_sync(0xffffffffu, rm0, 1));
        rm0 = fmaxf(rm0, __shfl_xor_sync(0xffffffffu, rm0, 2));
        rm1 = fmaxf(rm1, __shfl_xor_sync(0xffffffffu, rm1, 1));
        rm1 = fmaxf(rm1, __shfl_xor_sync(0xffffffffu, rm1, 2));

        const float mn0 = fmaxf(m0r, rm0), mn1 = fmaxf(m1r, rm1);
        const float a0 = __expf(m0r - mn0), a1 = __expf(m1r - mn1);
        m0r = mn0; m1r = mn1;

        float rs0 = 0.f, rs1 = 0.f;
        #pragma unroll
        for (int j = 0; j < 8; j++) {
            s[j][0] = __expf(s[j][0] - mn0);
            s[j][1] = __expf(s[j][1] - mn0);
            s[j][2] = __expf(s[j][2] - mn1);
            s[j][3] = __expf(s[j][3] - mn1);
            rs0 += s[j][0] + s[j][1];
            rs1 += s[j][2] + s[j][3];
        }
        rs0 += __shfl_xor_sync(0xffffffffu, rs0, 1);
        rs0 += __shfl_xor_sync(0xffffffffu, rs0, 2);
        rs1 += __shfl_xor_sync(0xffffffffu, rs1, 1);
        rs1 += __shfl_xor_sync(0xffffffffu, rs1, 2);
        l0 = l0 * a0 + rs0;
        l1 = l1 * a1 + rs1;
        #pragma unroll
        for (int d = 0; d < 8; d++) {
            o[d][0] *= a0; o[d][1] *= a0;
            o[d][2] *= a1; o[d][3] *= a1;
        }

        // Store P to per-warp band of Ps (tf32)
        #pragma unroll
        for (int j = 0; j < 8; j++) {
            const int base = mrow * AS2 + j * 8 + qc * 2;
            Ps[base]     = __uint_as_float(f2tf32(s[j][0]));
            Ps[base + 1] = __uint_as_float(f2tf32(s[j][1]));
            Ps[base + 8 * AS2]     = __uint_as_float(f2tf32(s[j][2]));
            Ps[base + 8 * AS2 + 1] = __uint_as_float(f2tf32(s[j][3]));
        }
        __syncwarp();

        // O += P @ V
        #pragma unroll
        for (int ks = 0; ks < 8; ks++) {
            const int k0 = ks * 8 + qc;
            uint32_t pa[4];
            pa[0] = __float_as_uint(Ps[mrow * AS2 + k0]);
            pa[1] = __float_as_uint(Ps[(mrow + 8) * AS2 + k0]);
            pa[2] = __float_as_uint(Ps[mrow * AS2 + k0 + 4]);
            pa[3] = __float_as_uint(Ps[(mrow + 8) * AS2 + k0 + 4]);
            #pragma unroll
            for (int d = 0; d < 8; d++) {
                uint32_t bf[2];
                const int n0 = d * 8 + qr;
                bf[0] = __float_as_uint(Vs[n0 * AS2 + k0]);
                bf[1] = __float_as_uint(Vs[n0 * AS2 + k0 + 4]);
                mma_tf32(o[d], pa, bf);
            }
        }
    }

    // Write normalized, tf32-rounded output (feeds proj GEMM)
    const float i0 = 1.0f / l0, i1 = 1.0f / l1;
    const size_t row0 = tok0 + q0 + mrow;
    #pragma unroll
    for (int d = 0; d < 8; d++) {
        const int col = h * 64 + d * 8 + qc * 2;
        *(float2*)(out + row0 * DMODEL + col) =
            make_float2(f2tf32f(o[d][0] * i0), f2tf32f(o[d][1] * i0));
        *(float2*)(out + (row0 + 8) * DMODEL + col) =
            make_float2(f2tf32f(o[d][2] * i1), f2tf32f(o[d][3] * i1));
    }
}

// ---------------------------------------------------------------------------
// Launch
// ---------------------------------------------------------------------------
extern "C" void kernel_launch(void* const* d_in, const int* in_sizes, int n_in,
                              void* d_out, int out_size)
{
    (void)in_sizes; (void)n_in; (void)out_size;
    const float* x      = (const float*)d_in[0];
    const float* qkv_w  = (const float*)d_in[1];
    const float* proj_w = (const float*)d_in[2];
    const float* proj_b = (const float*)d_in[3];
    const float* fc1_w  = (const float*)d_in[4];
    const float* fc1_b  = (const float*)d_in[5];
    const float* fc2_w  = (const float*)d_in[6];
    const float* fc2_b  = (const float*)d_in[7];
    const float* n1g    = (const float*)d_in[8];
    const float* n1b    = (const float*)d_in[9];
    const float* n2g    = (const float*)d_in[10];
    const float* n2b    = (const float*)d_in[11];
    float* out = (float*)d_out;

    float *big, *y, *attn, *x1, *w;
    cudaGetSymbolAddress((void**)&big,  g_big);
    cudaGetSymbolAddress((void**)&y,    g_y);
    cudaGetSymbolAddress((void**)&attn, g_attn);
    cudaGetSymbolAddress((void**)&x1,   g_x1);
    cudaGetSymbolAddress((void**)&w,    g_w);

    cudaFuncSetAttribute(gemm_tf32<EPI_NONE>,
                         cudaFuncAttributeMaxDynamicSharedMemorySize, GEMM_SMEM);
    cudaFuncSetAttribute(gemm_tf32<EPI_BIAS_RES>,
                         cudaFuncAttributeMaxDynamicSharedMemorySize, GEMM_SMEM);
    cudaFuncSetAttribute(gemm_tf32<EPI_BIAS_GELU>,
                         cudaFuncAttributeMaxDynamicSharedMemorySize, GEMM_SMEM);
    cudaFuncSetAttribute(attn_tc,
                         cudaFuncAttributeMaxDynamicSharedMemorySize, ATTN_SMEM);

    // Pre-round weights to tf32 (RNA) so cp.async raw bits are exact tf32.
    round_w_kernel<<<(QKVDIM * DMODEL / 4 + 255) / 256, 256>>>(qkv_w,  w + W_QKV,  QKVDIM * DMODEL / 4);
    round_w_kernel<<<(DMODEL * DMODEL / 4 + 255) / 256, 256>>>(proj_w, w + W_PROJ, DMODEL * DMODEL / 4);
    round_w_kernel<<<(HIDDEN * DMODEL / 4 + 255) / 256, 256>>>(fc1_w,  w + W_FC1,  HIDDEN * DMODEL / 4);
    round_w_kernel<<<(DMODEL * HIDDEN / 4 + 255) / 256, 256>>>(fc2_w,  w + W_FC2,  DMODEL * HIDDEN / 4);

    // x1 = x + Attn(LN1(x))
    ln_kernel<<<TOKENS, 256>>>(x, n1g, n1b, y);
    gemm_tf32<EPI_NONE><<<dim3(QKVDIM / 128, TOKENS / 128), 256, GEMM_SMEM>>>(
        y, w + W_QKV, nullptr, nullptr, big, TOKENS, QKVDIM, DMODEL);
    attn_tc<<<dim3(SEQ / 64, NHEADS, BATCH), 128, ATTN_SMEM>>>(big, attn);
    gemm_tf32<EPI_BIAS_RES><<<dim3(DMODEL / 128, TOKENS / 128), 256, GEMM_SMEM>>>(
        attn, w + W_PROJ, proj_b, x, x1, TOKENS, DMODEL, DMODEL);

    // out = x1 + MLP(LN2(x1))
    ln_kernel<<<TOKENS, 256>>>(x1, n2g, n2b, y);
    gemm_tf32<EPI_BIAS_GELU><<<dim3(HIDDEN / 128, TOKENS / 128), 256, GEMM_SMEM>>>(
        y, w + W_FC1, fc1_b, nullptr, big, TOKENS, HIDDEN, DMODEL);
    gemm_tf32<EPI_BIAS_RES><<<dim3(DMODEL / 128, TOKENS / 128), 256, GEMM_SMEM>>>(
        big, w + W_FC2, fc2_b, x1, out, TOKENS, DMODEL, HIDDEN);
}

// round 7
// speedup vs baseline: 4.3306x; 1.2217x over previous
#include <cuda_runtime.h>
#include <cuda_fp16.h>
#include <math.h>
#include <stdint.h>

// Problem constants
#define TOKENS   16384      // B*N
#define DMODEL   768
#define HIDDEN   3072
#define NHEADS   12
#define SEQ      1024
#define BATCH    16
#define QKVDIM   2304

// ---------------------------------------------------------------------------
// Scratch (static __device__ — no allocation allowed)
// ---------------------------------------------------------------------------
__device__ __align__(16) __half g_bigh[TOKENS * HIDDEN];   // qkv (half) OR gelu out (half)
__device__ __align__(16) __half g_yh[TOKENS * DMODEL];     // layernorm output (half)
__device__ __align__(16) __half g_attnh[TOKENS * DMODEL];  // attention output (half)
__device__ float g_x1[TOKENS * DMODEL];                    // residual-1 (exact fp32)
// half weights: qkv | proj | fc1 | fc2
#define W_QKV  0
#define W_PROJ (W_QKV + QKVDIM * DMODEL)
#define W_FC1  (W_PROJ + DMODEL * DMODEL)
#define W_FC2  (W_FC1 + HIDDEN * DMODEL)
#define W_TOT  (W_FC2 + DMODEL * HIDDEN)
__device__ __align__(16) __half g_wh[W_TOT];

// ---------------------------------------------------------------------------
// fp16 mma helpers
// ---------------------------------------------------------------------------
__device__ __forceinline__ void mma_f16(float* c, const uint32_t* a, const uint32_t* b) {
    asm volatile(
        "mma.sync.aligned.m16n8k16.row.col.f32.f16.f16.f32 "
        "{%0,%1,%2,%3}, {%4,%5,%6,%7}, {%8,%9}, {%0,%1,%2,%3};"
        : "+f"(c[0]), "+f"(c[1]), "+f"(c[2]), "+f"(c[3])
        : "r"(a[0]), "r"(a[1]), "r"(a[2]), "r"(a[3]), "r"(b[0]), "r"(b[1]));
}

__device__ __forceinline__ void cpa16(uint32_t dst, const void* src) {
    asm volatile("cp.async.cg.shared.global [%0], [%1], 16;\n" :: "r"(dst), "l"(src));
}

__device__ __forceinline__ uint32_t h2pack(float a, float b) {
    __half2 h = __floats2half2_rn(a, b);
    return *(uint32_t*)&h;
}

// ---------------------------------------------------------------------------
// Weight conversion: float -> half
// ---------------------------------------------------------------------------
__global__ __launch_bounds__(256) void cvt_w_kernel(
    const float* __restrict__ src, __half* __restrict__ dst, int n4)
{
    int i = blockIdx.x * blockDim.x + threadIdx.x;
    if (i < n4) {
        float4 v = ((const float4*)src)[i];
        uint32_t h0 = h2pack(v.x, v.y);
        uint32_t h1 = h2pack(v.z, v.w);
        ((uint2*)dst)[i] = make_uint2(h0, h1);
    }
}

// ---------------------------------------------------------------------------
// LayerNorm (fp32 math, half output — feeds GEMM A operands)
// ---------------------------------------------------------------------------
__global__ __launch_bounds__(256) void ln_kernel(
    const float* __restrict__ x, const float* __restrict__ g,
    const float* __restrict__ b, __half* __restrict__ y)
{
    const int row = blockIdx.x;
    const int tid = threadIdx.x;
    const float* xr = x + (size_t)row * DMODEL;

    float v0 = xr[tid];
    float v1 = xr[tid + 256];
    float v2 = xr[tid + 512];
    float s  = v0 + v1 + v2;
    float sq = v0 * v0 + v1 * v1 + v2 * v2;

    __shared__ float red[16];
    #pragma unroll
    for (int off = 16; off; off >>= 1) {
        s  += __shfl_xor_sync(0xffffffffu, s,  off);
        sq += __shfl_xor_sync(0xffffffffu, sq, off);
    }
    const int warp = tid >> 5;
    if ((tid & 31) == 0) { red[warp] = s; red[warp + 8] = sq; }
    __syncthreads();
    float ts = 0.f, tsq = 0.f;
    #pragma unroll
    for (int i = 0; i < 8; i++) { ts += red[i]; tsq += red[i + 8]; }

    const float mean = ts * (1.0f / DMODEL);
    const float var  = tsq * (1.0f / DMODEL) - mean * mean;
    const float rstd = rsqrtf(var + 1e-6f);

    __half* yr = y + (size_t)row * DMODEL;
    yr[tid]       = __float2half_rn((v0 - mean) * rstd * g[tid]       + b[tid]);
    yr[tid + 256] = __float2half_rn((v1 - mean) * rstd * g[tid + 256] + b[tid + 256]);
    yr[tid + 512] = __float2half_rn((v2 - mean) * rstd * g[tid + 512] + b[tid + 512]);
}

// ---------------------------------------------------------------------------
// FP16 NT GEMM, cp.async 3-stage pipeline, m16n8k16 mma.
// C[M,N] = A[M,K] @ B[N,K]^T, A/B half (producer-rounded), accum fp32.
// 128x128 CTA tile, BK=64 halves (4 k16 steps), 256 thr = 8 warps (2x4),
// warp 64x32 as 4x4 m16n8k16. Smem stride 72 halves (36 words) ->
// fragment reads bank-conflict-free ((36g+qc)%32 = (4g+qc)%32, all distinct).
// ---------------------------------------------------------------------------
#define BKH  64
#define KSTH 72
#define KSTW 36
#define STAGE_BYTES (2 * 128 * KSTH * 2)   // 36864: A 18432 + B 18432
#define STAGES 3
#define GEMM_SMEM (STAGES * STAGE_BYTES)   // 110592

enum { EPI_NONE = 0, EPI_BIAS_RES = 1, EPI_BIAS_GELU = 2 };

template <int EPI>
__global__ __launch_bounds__(256, 2) void gemm_f16(
    const __half* __restrict__ A, const __half* __restrict__ B,
    const float* __restrict__ bias, const float* __restrict__ res,
    void* __restrict__ Cv, int M, int N, int K)
{
    extern __shared__ char smem[];

    const int tid = threadIdx.x;
    const int bm = blockIdx.y, bn = blockIdx.x;

    const __half* Abase = A + (size_t)(bm * 128) * K;
    const __half* Bbase = B + (size_t)(bn * 128) * K;

    const uint32_t sbase = (uint32_t)__cvta_generic_to_shared(smem);

    const int wid = tid >> 5, lane = tid & 31;
    const int wm = (wid >> 2) * 64;
    const int wn = (wid & 3) * 32;
    const int qr = lane >> 2;           // groupID
    const int qc = lane & 3;            // threadID-in-group

    float acc[4][4][4];
    #pragma unroll
    for (int i = 0; i < 4; i++)
        #pragma unroll
        for (int j = 0; j < 4; j++)
            #pragma unroll
            for (int t = 0; t < 4; t++) acc[i][j][t] = 0.f;

    const int kT = K / BKH;

    // loader: stage sb gets K-chunk kc. 4 A-chunks + 4 B-chunks per thread.
    #define LOAD_TILE(kc)                                                       \
        do {                                                                    \
            const uint32_t sb = sbase + ((kc) % STAGES) * STAGE_BYTES;          \
            const int k0 = (kc) * BKH;                                          \
            _Pragma("unroll")                                                   \
            for (int i = 0; i < 4; i++) {                                       \
                const int idx = i * 256 + tid;                                  \
                const int r = idx >> 3, c = (idx & 7) * 8;                      \
                cpa16(sb + r * (KSTH * 2) + c * 2, Abase + (size_t)r * K + k0 + c); \
            }                                                                   \
            _Pragma("unroll")                                                   \
            for (int i = 0; i < 4; i++) {                                       \
                const int idx = i * 256 + tid;                                  \
                const int r = idx >> 3, c = (idx & 7) * 8;                      \
                cpa16(sb + 128 * KSTH * 2 + r * (KSTH * 2) + c * 2,             \
                      Bbase + (size_t)r * K + k0 + c);                          \
            }                                                                   \
        } while (0)

    #pragma unroll
    for (int p = 0; p < STAGES - 1; p++) {
        LOAD_TILE(p);
        asm volatile("cp.async.commit_group;");
    }

    for (int kt = 0; kt < kT; kt++) {
        asm volatile("cp.async.wait_group %0;" :: "n"(STAGES - 2));
        __syncthreads();

        const int nk = kt + STAGES - 1;
        if (nk < kT) LOAD_TILE(nk);
        asm volatile("cp.async.commit_group;");

        const uint32_t* As = (const uint32_t*)(smem + (kt % STAGES) * STAGE_BYTES);
        const uint32_t* Bs = As + 128 * KSTW;

        #pragma unroll
        for (int s = 0; s < 4; s++) {
            const int k0w = s * 8 + qc;
            uint32_t af[4][4], bf[4][2];
            #pragma unroll
            for (int i = 0; i < 4; i++) {
                const int m0 = wm + i * 16 + qr;
                af[i][0] = As[m0 * KSTW + k0w];
                af[i][1] = As[(m0 + 8) * KSTW + k0w];
                af[i][2] = As[m0 * KSTW + k0w + 4];
                af[i][3] = As[(m0 + 8) * KSTW + k0w + 4];
            }
            #pragma unroll
            for (int j = 0; j < 4; j++) {
                const int n0 = wn + j * 8 + qr;
                bf[j][0] = Bs[n0 * KSTW + k0w];
                bf[j][1] = Bs[n0 * KSTW + k0w + 4];
            }
            #pragma unroll
            for (int i = 0; i < 4; i++)
                #pragma unroll
                for (int j = 0; j < 4; j++)
                    mma_f16(acc[i][j], af[i], bf[j]);
        }
    }

    // Epilogue. half output for NONE/GELU (feeds next GEMM); float for RES.
    #pragma unroll
    for (int i = 0; i < 4; i++) {
        const int gr0 = bm * 128 + wm + i * 16 + qr;
        #pragma unroll
        for (int j = 0; j < 4; j++) {
            const int gc = bn * 128 + wn + j * 8 + qc * 2;
            float v0 = acc[i][j][0], v1 = acc[i][j][1];
            float v2 = acc[i][j][2], v3 = acc[i][j][3];
            if (EPI == EPI_BIAS_RES) {
                const float b0 = bias[gc], b1 = bias[gc + 1];
                float* C = (float*)Cv;
                const float* r0 = res + (size_t)gr0 * N + gc;
                const float* r1 = res + (size_t)(gr0 + 8) * N + gc;
                v0 += b0 + r0[0]; v1 += b1 + r0[1];
                v2 += b0 + r1[0]; v3 += b1 + r1[1];
                *(float2*)(C + (size_t)gr0 * N + gc)       = make_float2(v0, v1);
                *(float2*)(C + (size_t)(gr0 + 8) * N + gc) = make_float2(v2, v3);
            } else {
                if (EPI == EPI_BIAS_GELU) {
                    const float b0 = bias[gc], b1 = bias[gc + 1];
                    v0 += b0; v1 += b1; v2 += b0; v3 += b1;
                    v0 = 0.5f * v0 * (1.0f + erff(v0 * 0.70710678118654752f));
                    v1 = 0.5f * v1 * (1.0f + erff(v1 * 0.70710678118654752f));
                    v2 = 0.5f * v2 * (1.0f + erff(v2 * 0.70710678118654752f));
                    v3 = 0.5f * v3 * (1.0f + erff(v3 * 0.70710678118654752f));
                }
                __half* C = (__half*)Cv;
                *(uint32_t*)(C + (size_t)gr0 * N + gc)       = h2pack(v0, v1);
                *(uint32_t*)(C + (size_t)(gr0 + 8) * N + gc) = h2pack(v2, v3);
            }
        }
    }
    #undef LOAD_TILE
}

// ---------------------------------------------------------------------------
// FP16 tensor-core flash attention. 64 queries/CTA, 4 warps.
// qkv is HALF (written by qkv GEMM). Kh: K tile [64 key][64 d] halves;
// Vs: V^T [64 d][64 key]; Ph: P [64 q][64 key]. Stride 72 halves (36 words).
// Warp w owns query rows w*16 + {qr, qr+8}; Q frags register-resident.
// ---------------------------------------------------------------------------
#define ASH 72
#define ASW 36
#define ATTN_SMEM (3 * 64 * ASH * 2)   // 27648 B

__global__ __launch_bounds__(128, 3) void attn_f16(
    const __half* __restrict__ qkv, __half* __restrict__ out)
{
    extern __shared__ char smm[];
    __half* Kh = (__half*)smm;
    __half* Vs = Kh + 64 * ASH;
    __half* Ph = Vs + 64 * ASH;
    uint32_t* Kw = (uint32_t*)Kh;
    uint32_t* Vw = (uint32_t*)Vs;
    uint32_t* Pw = (uint32_t*)Ph;

    const int tid = threadIdx.x;
    const int wid = tid >> 5, lane = tid & 31;
    const int qr = lane >> 2, qc = lane & 3;
    const int q0 = blockIdx.x * 64;
    const int h  = blockIdx.y;
    const int b  = blockIdx.z;
    const size_t tok0 = (size_t)b * SEQ;

    const __half* qbase = qkv + (tok0 + q0) * QKVDIM + h * 64;
    const __half* kbase = qkv + tok0 * QKVDIM + 768 + h * 64;
    const __half* vbase = qkv + tok0 * QKVDIM + 1536 + h * 64;

    // Stage Q (scaled by 1/8 — exact in fp16) into Kh: 64 rows x 8 uint4
    const __half2 sc = __floats2half2_rn(0.125f, 0.125f);
    #pragma unroll
    for (int c = tid; c < 512; c += 128) {
        const int r = c >> 3, col = (c & 7) * 8;
        uint4 v = *(const uint4*)(qbase + (size_t)r * QKVDIM + col);
        __half2* p = (__half2*)&v;
        #pragma unroll
        for (int t = 0; t < 4; t++) p[t] = __hmul2(p[t], sc);
        *(uint4*)(Kh + r * ASH + col) = v;
    }
    __syncthreads();

    // Q fragments: 4 k16-steps
    const int mrow = wid * 16 + qr;
    uint32_t qa[4][4];
    #pragma unroll
    for (int s = 0; s < 4; s++) {
        const int k0w = s * 8 + qc;
        qa[s][0] = Kw[mrow * ASW + k0w];
        qa[s][1] = Kw[(mrow + 8) * ASW + k0w];
        qa[s][2] = Kw[mrow * ASW + k0w + 4];
        qa[s][3] = Kw[(mrow + 8) * ASW + k0w + 4];
    }

    float o[8][4];
    #pragma unroll
    for (int d = 0; d < 8; d++)
        #pragma unroll
        for (int t = 0; t < 4; t++) o[d][t] = 0.f;
    float m0r = -1e30f, m1r = -1e30f, l0 = 0.f, l1 = 0.f;

    for (int kb = 0; kb < SEQ / 64; kb++) {
        __syncthreads();   // prev Kh/Vs reads done (and Q frags extracted)
        // K tile: straight copy, 64 rows x 8 uint4
        #pragma unroll
        for (int c = tid; c < 512; c += 128) {
            const int r = c >> 3, col = (c & 7) * 8;
            *(uint4*)(Kh + r * ASH + col) =
                *(const uint4*)(kbase + (size_t)(kb * 64 + r) * QKVDIM + col);
        }
        // V tile transposed: read 8 halves along d for key j, scatter
        #pragma unroll
        for (int c = tid; c < 512; c += 128) {
            const int j = c >> 3, d0 = (c & 7) * 8;
            uint4 v = *(const uint4*)(vbase + (size_t)(kb * 64 + j) * QKVDIM + d0);
            const __half* hv = (const __half*)&v;
            #pragma unroll
            for (int t = 0; t < 8; t++) Vs[(d0 + t) * ASH + j] = hv[t];
        }
        __syncthreads();

        // S = Q @ K^T : 8 n8-tiles x 4 k16-steps
        float s[8][4];
        #pragma unroll
        for (int j = 0; j < 8; j++)
            #pragma unroll
            for (int t = 0; t < 4; t++) s[j][t] = 0.f;
        #pragma unroll
        for (int ks = 0; ks < 4; ks++) {
            const int k0w = ks * 8 + qc;
            #pragma unroll
            for (int j = 0; j < 8; j++) {
                uint32_t bf[2];
                const int n0 = j * 8 + qr;
                bf[0] = Kw[n0 * ASW + k0w];
                bf[1] = Kw[n0 * ASW + k0w + 4];
                mma_f16(s[j], qa[ks], bf);
            }
        }

        // Online softmax (rows qr, qr+8; reduce across 4 qc lanes)
        float rm0 = -1e30f, rm1 = -1e30f;
        #pragma unroll
        for (int j = 0; j < 8; j++) {
            rm0 = fmaxf(rm0, fmaxf(s[j][0], s[j][1]));
            rm1 = fmaxf(rm1, fmaxf(s[j][2], s[j][3]));
        }
        rm0 = fmaxf(rm0, __shfl_xor_sync(0xffffffffu, rm0, 1));
        rm0 = fmaxf(rm0, __shfl_xor_sync(0xffffffffu, rm0, 2));
        rm1 = fmaxf(rm1, __shfl_xor_sync(0xffffffffu, rm1, 1));
        rm1 = fmaxf(rm1, __shfl_xor_sync(0xffffffffu, rm1, 2));

        const float mn0 = fmaxf(m0r, rm0), mn1 = fmaxf(m1r, rm1);
        const float a0 = __expf(m0r - mn0), a1 = __expf(m1r - mn1);
        m0r = mn0; m1r = mn1;

        float rs0 = 0.f, rs1 = 0.f;
        #pragma unroll
        for (int j = 0; j < 8; j++) {
            s[j][0] = __expf(s[j][0] - mn0);
            s[j][1] = __expf(s[j][1] - mn0);
            s[j][2] = __expf(s[j][2] - mn1);
            s[j][3] = __expf(s[j][3] - mn1);
            rs0 += s[j][0] + s[j][1];
            rs1 += s[j][2] + s[j][3];
        }
        rs0 += __shfl_xor_sync(0xffffffffu, rs0, 1);
        rs0 += __shfl_xor_sync(0xffffffffu, rs0, 2);
        rs1 += __shfl_xor_sync(0xffffffffu, rs1, 1);
        rs1 += __shfl_xor_sync(0xffffffffu, rs1, 2);
        l0 = l0 * a0 + rs0;
        l1 = l1 * a1 + rs1;
        #pragma unroll
        for (int d = 0; d < 8; d++) {
            o[d][0] *= a0; o[d][1] *= a0;
            o[d][2] *= a1; o[d][3] *= a1;
        }

        // P -> half, per-warp band of Ph
        #pragma unroll
        for (int j = 0; j < 8; j++) {
            const int wcol = j * 4 + qc;   // word col = (j*8 + qc*2)/2
            Pw[mrow * ASW + wcol]       = h2pack(s[j][0], s[j][1]);
            Pw[(mrow + 8) * ASW + wcol] = h2pack(s[j][2], s[j][3]);
        }
        __syncwarp();

        // O += P @ V : 4 k16-steps over keys, 8 d-tiles
        #pragma unroll
        for (int ks = 0; ks < 4; ks++) {
            const int k0w = ks * 8 + qc;
            uint32_t pa[4];
            pa[0] = Pw[mrow * ASW + k0w];
            pa[1] = Pw[(mrow + 8) * ASW + k0w];
            pa[2] = Pw[mrow * ASW + k0w + 4];
            pa[3] = Pw[(mrow + 8) * ASW + k0w + 4];
            #pragma unroll
            for (int d = 0; d < 8; d++) {
                uint32_t bf[2];
                const int n0 = d * 8 + qr;
                bf[0] = Vw[n0 * ASW + k0w];
                bf[1] = Vw[n0 * ASW + k0w + 4];
                mma_f16(o[d], pa, bf);
            }
        }
    }

    // Normalize, write half output (feeds proj GEMM)
    const float i0 = 1.0f / l0, i1 = 1.0f / l1;
    const size_t row0 = tok0 + q0 + mrow;
    #pragma unroll
    for (int d = 0; d < 8; d++) {
        const int col = h * 64 + d * 8 + qc * 2;
        *(uint32_t*)(out + row0 * DMODEL + col)       = h2pack(o[d][0] * i0, o[d][1] * i0);
        *(uint32_t*)(out + (row0 + 8) * DMODEL + col) = h2pack(o[d][2] * i1, o[d][3] * i1);
    }
}

// ---------------------------------------------------------------------------
// Launch
// ---------------------------------------------------------------------------
extern "C" void kernel_launch(void* const* d_in, const int* in_sizes, int n_in,
                              void* d_out, int out_size)
{
    (void)in_sizes; (void)n_in; (void)out_size;
    const float* x      = (const float*)d_in[0];
    const float* qkv_w  = (const float*)d_in[1];
    const float* proj_w = (const float*)d_in[2];
    const float* proj_b = (const float*)d_in[3];
    const float* fc1_w  = (const float*)d_in[4];
    const float* fc1_b  = (const float*)d_in[5];
    const float* fc2_w  = (const float*)d_in[6];
    const float* fc2_b  = (const float*)d_in[7];
    const float* n1g    = (const float*)d_in[8];
    const float* n1b    = (const float*)d_in[9];
    const float* n2g    = (const float*)d_in[10];
    const float* n2b    = (const float*)d_in[11];
    float* out = (float*)d_out;

    __half *bigh, *yh, *attnh, *wh;
    float *x1;
    cudaGetSymbolAddress((void**)&bigh,  g_bigh);
    cudaGetSymbolAddress((void**)&yh,    g_yh);
    cudaGetSymbolAddress((void**)&attnh, g_attnh);
    cudaGetSymbolAddress((void**)&x1,    g_x1);
    cudaGetSymbolAddress((void**)&wh,    g_wh);

    cudaFuncSetAttribute(gemm_f16<EPI_NONE>,
                         cudaFuncAttributeMaxDynamicSharedMemorySize, GEMM_SMEM);
    cudaFuncSetAttribute(gemm_f16<EPI_BIAS_RES>,
                         cudaFuncAttributeMaxDynamicSharedMemorySize, GEMM_SMEM);
    cudaFuncSetAttribute(gemm_f16<EPI_BIAS_GELU>,
                         cudaFuncAttributeMaxDynamicSharedMemorySize, GEMM_SMEM);
    cudaFuncSetAttribute(attn_f16,
                         cudaFuncAttributeMaxDynamicSharedMemorySize, ATTN_SMEM);

    // Convert weights to half once per launch (graph-capturable, deterministic)
    cvt_w_kernel<<<(QKVDIM * DMODEL / 4 + 255) / 256, 256>>>(qkv_w,  wh + W_QKV,  QKVDIM * DMODEL / 4);
    cvt_w_kernel<<<(DMODEL * DMODEL / 4 + 255) / 256, 256>>>(proj_w, wh + W_PROJ, DMODEL * DMODEL / 4);
    cvt_w_kernel<<<(HIDDEN * DMODEL / 4 + 255) / 256, 256>>>(fc1_w,  wh + W_FC1,  HIDDEN * DMODEL / 4);
    cvt_w_kernel<<<(DMODEL * HIDDEN / 4 + 255) / 256, 256>>>(fc2_w,  wh + W_FC2,  DMODEL * HIDDEN / 4);

    // x1 = x + Attn(LN1(x))
    ln_kernel<<<TOKENS, 256>>>(x, n1g, n1b, yh);
    gemm_f16<EPI_NONE><<<dim3(QKVDIM / 128, TOKENS / 128), 256, GEMM_SMEM>>>(
        yh, wh + W_QKV, nullptr, nullptr, bigh, TOKENS, QKVDIM, DMODEL);
    attn_f16<<<dim3(SEQ / 64, NHEADS, BATCH), 128, ATTN_SMEM>>>(bigh, attnh);
    gemm_f16<EPI_BIAS_RES><<<dim3(DMODEL / 128, TOKENS / 128), 256, GEMM_SMEM>>>(
        attnh, wh + W_PROJ, proj_b, x, x1, TOKENS, DMODEL, DMODEL);

    // out = x1 + MLP(LN2(x1))
    ln_kernel<<<TOKENS, 256>>>(x1, n2g, n2b, yh);
    gemm_f16<EPI_BIAS_GELU><<<dim3(HIDDEN / 128, TOKENS / 128), 256, GEMM_SMEM>>>(
        yh, wh + W_FC1, fc1_b, nullptr, bigh, TOKENS, HIDDEN, DMODEL);
    gemm_f16<EPI_BIAS_RES><<<dim3(DMODEL / 128, TOKENS / 128), 256, GEMM_SMEM>>>(
        bigh, wh + W_FC2, fc2_b, x1, out, TOKENS, DMODEL, HIDDEN);
}

// round 8
// speedup vs baseline: 8.5123x; 1.9656x over previous
#include <cuda_runtime.h>
#include <cuda_fp16.h>
#include <math.h>
#include <stdint.h>

// Problem constants
#define TOKENS   16384      // B*N
#define DMODEL   768
#define HIDDEN   3072
#define NHEADS   12
#define SEQ      1024
#define BATCH    16
#define QKVDIM   2304

// ---------------------------------------------------------------------------
// Scratch (static __device__ — no allocation allowed)
// ---------------------------------------------------------------------------
__device__ __align__(16) __half g_bigh[TOKENS * HIDDEN];   // qkv (half) OR gelu out (half)
__device__ __align__(16) __half g_yh[TOKENS * DMODEL];     // layernorm output (half)
__device__ __align__(16) __half g_attnh[TOKENS * DMODEL];  // attention output (half)
__device__ float g_x1[TOKENS * DMODEL];                    // residual-1 (exact fp32)
// half weights: qkv | proj | fc1 | fc2
#define W_QKV  0
#define W_PROJ (W_QKV + QKVDIM * DMODEL)
#define W_FC1  (W_PROJ + DMODEL * DMODEL)
#define W_FC2  (W_FC1 + HIDDEN * DMODEL)
#define W_TOT  (W_FC2 + DMODEL * HIDDEN)
__device__ __align__(16) __half g_wh[W_TOT];

// ---------------------------------------------------------------------------
// fp16 mma / ldmatrix helpers
// ---------------------------------------------------------------------------
__device__ __forceinline__ void mma_f16(float* c, const uint32_t* a, const uint32_t* b) {
    asm volatile(
        "mma.sync.aligned.m16n8k16.row.col.f32.f16.f16.f32 "
        "{%0,%1,%2,%3}, {%4,%5,%6,%7}, {%8,%9}, {%0,%1,%2,%3};"
        : "+f"(c[0]), "+f"(c[1]), "+f"(c[2]), "+f"(c[3])
        : "r"(a[0]), "r"(a[1]), "r"(a[2]), "r"(a[3]), "r"(b[0]), "r"(b[1]));
}

#define LDSM4(r, addr)                                                          \
    asm volatile("ldmatrix.sync.aligned.m8n8.x4.shared.b16 {%0,%1,%2,%3}, [%4];" \
                 : "=r"((r)[0]), "=r"((r)[1]), "=r"((r)[2]), "=r"((r)[3])       \
                 : "r"(addr))

#define LDSM4T(r, addr)                                                         \
    asm volatile("ldmatrix.sync.aligned.m8n8.x4.trans.shared.b16 {%0,%1,%2,%3}, [%4];" \
                 : "=r"((r)[0]), "=r"((r)[1]), "=r"((r)[2]), "=r"((r)[3])       \
                 : "r"(addr))

__device__ __forceinline__ void cpa16(uint32_t dst, const void* src) {
    asm volatile("cp.async.cg.shared.global [%0], [%1], 16;\n" :: "r"(dst), "l"(src));
}

__device__ __forceinline__ uint32_t h2pack(float a, float b) {
    __half2 h = __floats2half2_rn(a, b);
    return *(uint32_t*)&h;
}

// ---------------------------------------------------------------------------
// Weight conversion: float -> half
// ---------------------------------------------------------------------------
__global__ __launch_bounds__(256) void cvt_w_kernel(
    const float* __restrict__ src, __half* __restrict__ dst, int n4)
{
    int i = blockIdx.x * blockDim.x + threadIdx.x;
    if (i < n4) {
        float4 v = ((const float4*)src)[i];
        ((uint2*)dst)[i] = make_uint2(h2pack(v.x, v.y), h2pack(v.z, v.w));
    }
}

// ---------------------------------------------------------------------------
// LayerNorm (fp32 math, half output)
// ---------------------------------------------------------------------------
__global__ __launch_bounds__(256) void ln_kernel(
    const float* __restrict__ x, const float* __restrict__ g,
    const float* __restrict__ b, __half* __restrict__ y)
{
    const int row = blockIdx.x;
    const int tid = threadIdx.x;
    const float* xr = x + (size_t)row * DMODEL;

    float v0 = xr[tid];
    float v1 = xr[tid + 256];
    float v2 = xr[tid + 512];
    float s  = v0 + v1 + v2;
    float sq = v0 * v0 + v1 * v1 + v2 * v2;

    __shared__ float red[16];
    #pragma unroll
    for (int off = 16; off; off >>= 1) {
        s  += __shfl_xor_sync(0xffffffffu, s,  off);
        sq += __shfl_xor_sync(0xffffffffu, sq, off);
    }
    const int warp = tid >> 5;
    if ((tid & 31) == 0) { red[warp] = s; red[warp + 8] = sq; }
    __syncthreads();
    float ts = 0.f, tsq = 0.f;
    #pragma unroll
    for (int i = 0; i < 8; i++) { ts += red[i]; tsq += red[i + 8]; }

    const float mean = ts * (1.0f / DMODEL);
    const float var  = tsq * (1.0f / DMODEL) - mean * mean;
    const float rstd = rsqrtf(var + 1e-6f);

    __half* yr = y + (size_t)row * DMODEL;
    yr[tid]       = __float2half_rn((v0 - mean) * rstd * g[tid]       + b[tid]);
    yr[tid + 256] = __float2half_rn((v1 - mean) * rstd * g[tid + 256] + b[tid + 256]);
    yr[tid + 512] = __float2half_rn((v2 - mean) * rstd * g[tid + 512] + b[tid + 512]);
}

// ---------------------------------------------------------------------------
// FP16 NT GEMM, cp.async 3-stage pipeline, m16n8k16 mma, ldmatrix fragments.
// 128x128 CTA tile, BK=64 halves, 256 thr = 8 warps (2x4), warp 64x32.
// Row stride 72 halves (144B): ldmatrix row addrs in 16B units = 9r+c ->
// 8 rows hit 8 distinct 16B groups, conflict-free.
// ---------------------------------------------------------------------------
#define BKH  64
#define KSTH 72
#define ROWB (KSTH * 2)                    // 144 bytes
#define STAGE_BYTES (2 * 128 * ROWB)       // 36864
#define STAGES 3
#define GEMM_SMEM (STAGES * STAGE_BYTES)   // 110592

enum { EPI_NONE = 0, EPI_BIAS_RES = 1, EPI_BIAS_GELU = 2 };

template <int EPI>
__global__ __launch_bounds__(256, 2) void gemm_f16(
    const __half* __restrict__ A, const __half* __restrict__ B,
    const float* __restrict__ bias, const float* __restrict__ res,
    void* __restrict__ Cv, int M, int N, int K)
{
    extern __shared__ char smem[];

    const int tid = threadIdx.x;
    const int bm = blockIdx.y, bn = blockIdx.x;

    const __half* Abase = A + (size_t)(bm * 128) * K;
    const __half* Bbase = B + (size_t)(bn * 128) * K;

    const uint32_t sbase = (uint32_t)__cvta_generic_to_shared(smem);

    const int wid = tid >> 5, lane = tid & 31;
    const int wm = (wid >> 2) * 64;
    const int wn = (wid & 3) * 32;
    const int qr = lane >> 2;
    const int qc = lane & 3;

    // ldmatrix per-lane address components
    const int lane15 = lane & 15;
    const int lhk    = lane >> 4;                        // A: k-half select
    const int b_row  = (lane & 7) + ((lane >> 4) << 3);  // B: row within 16
    const int b_kh   = (lane >> 3) & 1;                  // B: k-half select
    const uint32_t laneA = (uint32_t)((wm + lane15) * ROWB + lhk * 16);
    const uint32_t laneB = (uint32_t)(128 * ROWB + (wn + b_row) * ROWB + b_kh * 16);

    float acc[4][4][4];
    #pragma unroll
    for (int i = 0; i < 4; i++)
        #pragma unroll
        for (int j = 0; j < 4; j++)
            #pragma unroll
            for (int t = 0; t < 4; t++) acc[i][j][t] = 0.f;

    const int kT = K / BKH;

    #define LOAD_TILE(kc)                                                       \
        do {                                                                    \
            const uint32_t sb = sbase + ((kc) % STAGES) * STAGE_BYTES;          \
            const int k0 = (kc) * BKH;                                          \
            _Pragma("unroll")                                                   \
            for (int i = 0; i < 4; i++) {                                       \
                const int idx = i * 256 + tid;                                  \
                const int r = idx >> 3, c = (idx & 7) * 8;                      \
                cpa16(sb + r * ROWB + c * 2, Abase + (size_t)r * K + k0 + c);   \
            }                                                                   \
            _Pragma("unroll")                                                   \
            for (int i = 0; i < 4; i++) {                                       \
                const int idx = i * 256 + tid;                                  \
                const int r = idx >> 3, c = (idx & 7) * 8;                      \
                cpa16(sb + 128 * ROWB + r * ROWB + c * 2,                       \
                      Bbase + (size_t)r * K + k0 + c);                          \
            }                                                                   \
        } while (0)

    #pragma unroll
    for (int p = 0; p < STAGES - 1; p++) {
        LOAD_TILE(p);
        asm volatile("cp.async.commit_group;");
    }

    for (int kt = 0; kt < kT; kt++) {
        asm volatile("cp.async.wait_group %0;" :: "n"(STAGES - 2));
        __syncthreads();

        const int nk = kt + STAGES - 1;
        if (nk < kT) LOAD_TILE(nk);
        asm volatile("cp.async.commit_group;");

        const uint32_t sA = sbase + (kt % STAGES) * STAGE_BYTES + laneA;
        const uint32_t sB = sbase + (kt % STAGES) * STAGE_BYTES + laneB;

        #pragma unroll
        for (int s = 0; s < 4; s++) {
            const uint32_t k0b = s * 32;
            uint32_t af[4][4], bf[2][4];
            #pragma unroll
            for (int i = 0; i < 4; i++)
                LDSM4(af[i], sA + i * 16 * ROWB + k0b);
            #pragma unroll
            for (int jj = 0; jj < 2; jj++)
                LDSM4(bf[jj], sB + jj * 16 * ROWB + k0b);
            #pragma unroll
            for (int i = 0; i < 4; i++)
                #pragma unroll
                for (int j = 0; j < 4; j++)
                    mma_f16(acc[i][j], af[i], &bf[j >> 1][(j & 1) * 2]);
        }
    }

    // Epilogue: half for NONE/GELU (feeds next GEMM); float for RES.
    #pragma unroll
    for (int i = 0; i < 4; i++) {
        const int gr0 = bm * 128 + wm + i * 16 + qr;
        #pragma unroll
        for (int j = 0; j < 4; j++) {
            const int gc = bn * 128 + wn + j * 8 + qc * 2;
            float v0 = acc[i][j][0], v1 = acc[i][j][1];
            float v2 = acc[i][j][2], v3 = acc[i][j][3];
            if (EPI == EPI_BIAS_RES) {
                const float b0 = bias[gc], b1 = bias[gc + 1];
                float* C = (float*)Cv;
                const float* r0 = res + (size_t)gr0 * N + gc;
                const float* r1 = res + (size_t)(gr0 + 8) * N + gc;
                v0 += b0 + r0[0]; v1 += b1 + r0[1];
                v2 += b0 + r1[0]; v3 += b1 + r1[1];
                *(float2*)(C + (size_t)gr0 * N + gc)       = make_float2(v0, v1);
                *(float2*)(C + (size_t)(gr0 + 8) * N + gc) = make_float2(v2, v3);
            } else {
                if (EPI == EPI_BIAS_GELU) {
                    const float b0 = bias[gc], b1 = bias[gc + 1];
                    v0 += b0; v1 += b1; v2 += b0; v3 += b1;
                    v0 = 0.5f * v0 * (1.0f + erff(v0 * 0.70710678118654752f));
                    v1 = 0.5f * v1 * (1.0f + erff(v1 * 0.70710678118654752f));
                    v2 = 0.5f * v2 * (1.0f + erff(v2 * 0.70710678118654752f));
                    v3 = 0.5f * v3 * (1.0f + erff(v3 * 0.70710678118654752f));
                }
                __half* C = (__half*)Cv;
                *(uint32_t*)(C + (size_t)gr0 * N + gc)       = h2pack(v0, v1);
                *(uint32_t*)(C + (size_t)(gr0 + 8) * N + gc) = h2pack(v2, v3);
            }
        }
    }
    #undef LOAD_TILE
}

// ---------------------------------------------------------------------------
// FP16 flash attention, ldmatrix everywhere, no P smem round trip.
// 64 q/CTA, 4 warps. Kh: [64 key][64 d]; Vs: [64 key][64 d] (untransposed —
// V^T fragments loaded with ldmatrix.trans). P converts C-frag -> A-frag in
// registers. Smem = 2 tiles only.
// ---------------------------------------------------------------------------
#define ASH 72
#define AROWB (ASH * 2)                 // 144 bytes
#define ATTN_SMEM (2 * 64 * AROWB)      // 18432

__global__ __launch_bounds__(128, 4) void attn_f16(
    const __half* __restrict__ qkv, __half* __restrict__ out)
{
    extern __shared__ char smm[];
    __half* Kh = (__half*)smm;
    __half* Vs = Kh + 64 * ASH;
    const uint32_t sK = (uint32_t)__cvta_generic_to_shared(Kh);
    const uint32_t sV = (uint32_t)__cvta_generic_to_shared(Vs);

    const int tid = threadIdx.x;
    const int wid = tid >> 5, lane = tid & 31;
    const int qr = lane >> 2, qc = lane & 3;
    const int q0 = blockIdx.x * 64;
    const int h  = blockIdx.y;
    const int b  = blockIdx.z;
    const size_t tok0 = (size_t)b * SEQ;

    const __half* qbase = qkv + (tok0 + q0) * QKVDIM + h * 64;
    const __half* kbase = qkv + tok0 * QKVDIM + 768 + h * 64;
    const __half* vbase = qkv + tok0 * QKVDIM + 1536 + h * 64;

    // ldmatrix per-lane address components
    const int lane15 = lane & 15;
    const int lhk    = lane >> 4;
    const int b_row  = (lane & 7) + ((lane >> 4) << 3);
    const int b_kh   = (lane >> 3) & 1;
    // V-trans: row = key within 16 (k-half via bit3), col-tile via bit4
    const int v_row  = (lane & 7) + (((lane >> 3) & 1) << 3);
    const int v_ct   = lane >> 4;

    // Stage Q (scaled 1/8, exact) into Kh, extract fragments via ldmatrix
    const __half2 sc = __floats2half2_rn(0.125f, 0.125f);
    #pragma unroll
    for (int c = tid; c < 512; c += 128) {
        const int r = c >> 3, col = (c & 7) * 8;
        uint4 v = *(const uint4*)(qbase + (size_t)r * QKVDIM + col);
        __half2* p = (__half2*)&v;
        #pragma unroll
        for (int t = 0; t < 4; t++) p[t] = __hmul2(p[t], sc);
        *(uint4*)(Kh + r * ASH + col) = v;
    }
    __syncthreads();

    const int mrow = wid * 16 + qr;
    const uint32_t qlane = sK + (uint32_t)((wid * 16 + lane15) * AROWB + lhk * 16);
    uint32_t qa[4][4];
    #pragma unroll
    for (int s = 0; s < 4; s++) LDSM4(qa[s], qlane + s * 32);

    float o[8][4];
    #pragma unroll
    for (int d = 0; d < 8; d++)
        #pragma unroll
        for (int t = 0; t < 4; t++) o[d][t] = 0.f;
    float m0r = -1e30f, m1r = -1e30f, l0 = 0.f, l1 = 0.f;

    const uint32_t klane = sK + (uint32_t)(b_row * AROWB + b_kh * 16);
    const uint32_t vlane = sV + (uint32_t)(v_row * AROWB + v_ct * 16);

    for (int kb = 0; kb < SEQ / 64; kb++) {
        __syncthreads();   // prev Kh/Vs reads done (Q frags already extracted)
        #pragma unroll
        for (int c = tid; c < 512; c += 128) {
            const int r = c >> 3, col = (c & 7) * 8;
            *(uint4*)(Kh + r * ASH + col) =
                *(const uint4*)(kbase + (size_t)(kb * 64 + r) * QKVDIM + col);
            *(uint4*)(Vs + r * ASH + col) =
                *(const uint4*)(vbase + (size_t)(kb * 64 + r) * QKVDIM + col);
        }
        __syncthreads();

        // S = Q @ K^T
        float s[8][4];
        #pragma unroll
        for (int j = 0; j < 8; j++)
            #pragma unroll
            for (int t = 0; t < 4; t++) s[j][t] = 0.f;
        #pragma unroll
        for (int ks = 0; ks < 4; ks++) {
            #pragma unroll
            for (int jj = 0; jj < 4; jj++) {
                uint32_t bf[4];
                LDSM4(bf, klane + jj * 16 * AROWB + ks * 32);
                mma_f16(s[2 * jj],     qa[ks], &bf[0]);
                mma_f16(s[2 * jj + 1], qa[ks], &bf[2]);
            }
        }

        // Online softmax (rows qr, qr+8; reduce across 4 qc lanes)
        float rm0 = -1e30f, rm1 = -1e30f;
        #pragma unroll
        for (int j = 0; j < 8; j++) {
            rm0 = fmaxf(rm0, fmaxf(s[j][0], s[j][1]));
            rm1 = fmaxf(rm1, fmaxf(s[j][2], s[j][3]));
        }
        rm0 = fmaxf(rm0, __shfl_xor_sync(0xffffffffu, rm0, 1));
        rm0 = fmaxf(rm0, __shfl_xor_sync(0xffffffffu, rm0, 2));
        rm1 = fmaxf(rm1, __shfl_xor_sync(0xffffffffu, rm1, 1));
        rm1 = fmaxf(rm1, __shfl_xor_sync(0xffffffffu, rm1, 2));

        const float mn0 = fmaxf(m0r, rm0), mn1 = fmaxf(m1r, rm1);
        const float a0 = __expf(m0r - mn0), a1 = __expf(m1r - mn1);
        m0r = mn0; m1r = mn1;

        float rs0 = 0.f, rs1 = 0.f;
        #pragma unroll
        for (int j = 0; j < 8; j++) {
            s[j][0] = __expf(s[j][0] - mn0);
            s[j][1] = __expf(s[j][1] - mn0);
            s[j][2] = __expf(s[j][2] - mn1);
            s[j][3] = __expf(s[j][3] - mn1);
            rs0 += s[j][0] + s[j][1];
            rs1 += s[j][2] + s[j][3];
        }
        rs0 += __shfl_xor_sync(0xffffffffu, rs0, 1);
        rs0 += __shfl_xor_sync(0xffffffffu, rs0, 2);
        rs1 += __shfl_xor_sync(0xffffffffu, rs1, 1);
        rs1 += __shfl_xor_sync(0xffffffffu, rs1, 2);
        l0 = l0 * a0 + rs0;
        l1 = l1 * a1 + rs1;
        #pragma unroll
        for (int d = 0; d < 8; d++) {
            o[d][0] *= a0; o[d][1] *= a0;
            o[d][2] *= a1; o[d][3] *= a1;
        }

        // P: C-frag -> A-frag, pure registers (k-step ks spans tiles 2ks,2ks+1)
        uint32_t pa[4][4];
        #pragma unroll
        for (int ks = 0; ks < 4; ks++) {
            pa[ks][0] = h2pack(s[2 * ks][0],     s[2 * ks][1]);
            pa[ks][1] = h2pack(s[2 * ks][2],     s[2 * ks][3]);
            pa[ks][2] = h2pack(s[2 * ks + 1][0], s[2 * ks + 1][1]);
            pa[ks][3] = h2pack(s[2 * ks + 1][2], s[2 * ks + 1][3]);
        }

        // O += P @ V  (V^T fragments via ldmatrix.trans from [key][d] tile)
        #pragma unroll
        for (int ks = 0; ks < 4; ks++) {
            #pragma unroll
            for (int dd = 0; dd < 4; dd++) {
                uint32_t bf[4];
                LDSM4T(bf, vlane + ks * 16 * AROWB + dd * 32);
                mma_f16(o[2 * dd],     pa[ks], &bf[0]);
                mma_f16(o[2 * dd + 1], pa[ks], &bf[2]);
            }
        }
    }

    // Normalize, write half output (feeds proj GEMM)
    const float i0 = 1.0f / l0, i1 = 1.0f / l1;
    const size_t row0 = tok0 + q0 + mrow;
    #pragma unroll
    for (int d = 0; d < 8; d++) {
        const int col = h * 64 + d * 8 + qc * 2;
        *(uint32_t*)(out + row0 * DMODEL + col)       = h2pack(o[d][0] * i0, o[d][1] * i0);
        *(uint32_t*)(out + (row0 + 8) * DMODEL + col) = h2pack(o[d][2] * i1, o[d][3] * i1);
    }
}

// ---------------------------------------------------------------------------
// Launch
// ---------------------------------------------------------------------------
extern "C" void kernel_launch(void* const* d_in, const int* in_sizes, int n_in,
                              void* d_out, int out_size)
{
    (void)in_sizes; (void)n_in; (void)out_size;
    const float* x      = (const float*)d_in[0];
    const float* qkv_w  = (const float*)d_in[1];
    const float* proj_w = (const float*)d_in[2];
    const float* proj_b = (const float*)d_in[3];
    const float* fc1_w  = (const float*)d_in[4];
    const float* fc1_b  = (const float*)d_in[5];
    const float* fc2_w  = (const float*)d_in[6];
    const float* fc2_b  = (const float*)d_in[7];
    const float* n1g    = (const float*)d_in[8];
    const float* n1b    = (const float*)d_in[9];
    const float* n2g    = (const float*)d_in[10];
    const float* n2b    = (const float*)d_in[11];
    float* out = (float*)d_out;

    __half *bigh, *yh, *attnh, *wh;
    float *x1;
    cudaGetSymbolAddress((void**)&bigh,  g_bigh);
    cudaGetSymbolAddress((void**)&yh,    g_yh);
    cudaGetSymbolAddress((void**)&attnh, g_attnh);
    cudaGetSymbolAddress((void**)&x1,    g_x1);
    cudaGetSymbolAddress((void**)&wh,    g_wh);

    cudaFuncSetAttribute(gemm_f16<EPI_NONE>,
                         cudaFuncAttributeMaxDynamicSharedMemorySize, GEMM_SMEM);
    cudaFuncSetAttribute(gemm_f16<EPI_BIAS_RES>,
                         cudaFuncAttributeMaxDynamicSharedMemorySize, GEMM_SMEM);
    cudaFuncSetAttribute(gemm_f16<EPI_BIAS_GELU>,
                         cudaFuncAttributeMaxDynamicSharedMemorySize, GEMM_SMEM);
    cudaFuncSetAttribute(attn_f16,
                         cudaFuncAttributeMaxDynamicSharedMemorySize, ATTN_SMEM);

    cvt_w_kernel<<<(QKVDIM * DMODEL / 4 + 255) / 256, 256>>>(qkv_w,  wh + W_QKV,  QKVDIM * DMODEL / 4);
    cvt_w_kernel<<<(DMODEL * DMODEL / 4 + 255) / 256, 256>>>(proj_w, wh + W_PROJ, DMODEL * DMODEL / 4);
    cvt_w_kernel<<<(HIDDEN * DMODEL / 4 + 255) / 256, 256>>>(fc1_w,  wh + W_FC1,  HIDDEN * DMODEL / 4);
    cvt_w_kernel<<<(DMODEL * HIDDEN / 4 + 255) / 256, 256>>>(fc2_w,  wh + W_FC2,  DMODEL * HIDDEN / 4);

    // x1 = x + Attn(LN1(x))
    ln_kernel<<<TOKENS, 256>>>(x, n1g, n1b, yh);
    gemm_f16<EPI_NONE><<<dim3(QKVDIM / 128, TOKENS / 128), 256, GEMM_SMEM>>>(
        yh, wh + W_QKV, nullptr, nullptr, bigh, TOKENS, QKVDIM, DMODEL);
    attn_f16<<<dim3(SEQ / 64, NHEADS, BATCH), 128, ATTN_SMEM>>>(bigh, attnh);
    gemm_f16<EPI_BIAS_RES><<<dim3(DMODEL / 128, TOKENS / 128), 256, GEMM_SMEM>>>(
        attnh, wh + W_PROJ, proj_b, x, x1, TOKENS, DMODEL, DMODEL);

    // out = x1 + MLP(LN2(x1))
    ln_kernel<<<TOKENS, 256>>>(x1, n2g, n2b, yh);
    gemm_f16<EPI_BIAS_GELU><<<dim3(HIDDEN / 128, TOKENS / 128), 256, GEMM_SMEM>>>(
        yh, wh + W_FC1, fc1_b, nullptr, bigh, TOKENS, HIDDEN, DMODEL);
    gemm_f16<EPI_BIAS_RES><<<dim3(DMODEL / 128, TOKENS / 128), 256, GEMM_SMEM>>>(
        bigh, wh + W_FC2, fc2_b, x1, out, TOKENS, DMODEL, HIDDEN);
}